// round 1
// baseline (speedup 1.0000x reference)
#include <cuda_runtime.h>
#include <math_constants.h>

#define B 32
#define H0 256
#define W0 256
#define NPIX (B*H0*W0)
#define BN_EPS 1e-3f

// ---------------- scratch (global device arrays; no allocation) ----------------
__device__ float g_MA[NPIX];
__device__ float g_MB[NPIX];
__device__ float g_XC[NPIX];
__device__ float g_Y1[(size_t)B*254*254*8];
__device__ float g_Y2[(size_t)B*126*126*16];
__device__ float g_Y3[(size_t)B*124*124*32];
__device__ float g_GM[B*32];
__device__ float g_H[B];

// ---------------- 3x3 morphology (erosion: min, -k reversed; dilation: max, +k) ----------------
template<bool ERO>
__global__ void morph_k(const float* __restrict__ in, float* __restrict__ out,
                        const float* __restrict__ k9) {
    int x = threadIdx.x;
    int y = blockIdx.x;
    int b = blockIdx.y;
    const float* base = in + (size_t)b*H0*W0;
    float best = ERO ? CUDART_INF_F : -CUDART_INF_F;
#pragma unroll
    for (int i = 0; i < 3; i++) {
        int yy = y + i - 1;
        if (yy < 0 || yy >= H0) continue;
#pragma unroll
        for (int j = 0; j < 3; j++) {
            int xx = x + j - 1;
            if (xx < 0 || xx >= W0) continue;
            float v = base[yy*W0 + xx];
            if (ERO) { v -= k9[(2-i)*3 + (2-j)]; best = fminf(best, v); }
            else     { v += k9[i*3 + j];         best = fmaxf(best, v); }
        }
    }
    out[(size_t)b*H0*W0 + y*W0 + x] = best;
}

// ---------------- conv1 (1->8) + relu + bn1 ----------------
__global__ void conv1_k(const float* __restrict__ xc, const float* __restrict__ w,
                        const float* __restrict__ bias,
                        const float* __restrict__ gg, const float* __restrict__ bb,
                        const float* __restrict__ mm, const float* __restrict__ vv,
                        float* __restrict__ out) {
    int t = threadIdx.x;
    int co = t & 7, xl = t >> 3;
    int x = blockIdx.x*32 + xl;
    int y = blockIdx.y, b = blockIdx.z;
    if (x >= 254) return;
    float acc = bias[co];
    const float* base = xc + ((size_t)b*H0 + y)*W0 + x;
#pragma unroll
    for (int i = 0; i < 3; i++)
#pragma unroll
        for (int j = 0; j < 3; j++)
            acc = fmaf(base[i*W0 + j], w[(i*3 + j)*8 + co], acc);
    acc = fmaxf(acc, 0.f);
    float sc = gg[co] * rsqrtf(vv[co] + BN_EPS);
    acc = sc * (acc - mm[co]) + bb[co];
    out[(((size_t)b*254 + y)*254 + x)*8 + co] = acc;
}

// ---------------- conv2 (8->16) + relu + maxpool2 + bn2, fused ----------------
__global__ void conv2_k(const float* __restrict__ y1, const float* __restrict__ w,
                        const float* __restrict__ bias,
                        const float* __restrict__ gg, const float* __restrict__ bb,
                        const float* __restrict__ mm, const float* __restrict__ vv,
                        float* __restrict__ out) {
    __shared__ float sw[1152];  // 3*3*8*16
    int t = threadIdx.x;
    for (int i = t; i < 1152; i += 256) sw[i] = w[i];
    __syncthreads();
    int co = t & 15, xl = t >> 4;
    int q = blockIdx.x*16 + xl;     // pooled col
    int p = blockIdx.y, b = blockIdx.z;
    if (q >= 126) return;
    float mx = -CUDART_INF_F;
#pragma unroll
    for (int dy = 0; dy < 2; dy++)
#pragma unroll
    for (int dx = 0; dx < 2; dx++) {
        float s = bias[co];
#pragma unroll
        for (int i = 0; i < 3; i++) {
            const float* row = y1 + (((size_t)b*254 + (2*p + dy + i))*254 + (2*q + dx))*8;
#pragma unroll
            for (int j = 0; j < 3; j++)
#pragma unroll
                for (int ci = 0; ci < 8; ci++)
                    s = fmaf(row[j*8 + ci], sw[((i*3 + j)*8 + ci)*16 + co], s);
        }
        mx = fmaxf(mx, fmaxf(s, 0.f));
    }
    float sc = gg[co] * rsqrtf(vv[co] + BN_EPS);
    out[(((size_t)b*126 + p)*126 + q)*16 + co] = sc * (mx - mm[co]) + bb[co];
}

// ---------------- conv3 (16->32) + relu + bn3 ----------------
__global__ void conv3_k(const float* __restrict__ y2, const float* __restrict__ w,
                        const float* __restrict__ bias,
                        const float* __restrict__ gg, const float* __restrict__ bb,
                        const float* __restrict__ mm, const float* __restrict__ vv,
                        float* __restrict__ out) {
    __shared__ float sw[4608];  // 3*3*16*32
    int t = threadIdx.x;
    for (int i = t; i < 4608; i += 256) sw[i] = w[i];
    __syncthreads();
    int co = t & 31, xl = t >> 5;
    int x = blockIdx.x*8 + xl;
    int y = blockIdx.y, b = blockIdx.z;
    if (x >= 124) return;
    float s = bias[co];
#pragma unroll
    for (int i = 0; i < 3; i++) {
        const float* row = y2 + (((size_t)b*126 + (y + i))*126 + x)*16;
#pragma unroll
        for (int j = 0; j < 3; j++)
#pragma unroll
            for (int ci = 0; ci < 16; ci++)
                s = fmaf(row[j*16 + ci], sw[((i*3 + j)*16 + ci)*32 + co], s);
    }
    s = fmaxf(s, 0.f);
    float sc = gg[co] * rsqrtf(vv[co] + BN_EPS);
    out[(((size_t)b*124 + y)*124 + x)*32 + co] = sc * (s - mm[co]) + bb[co];
}

// ---------------- conv4 (32->32) + relu + global spatial max (pool dropped: max o pool == max) ----------------
__global__ void conv4_k(const float* __restrict__ y3, const float* __restrict__ w,
                        const float* __restrict__ bias, float* __restrict__ gm) {
    __shared__ float sw[9216];  // 3*3*32*32
    int t = threadIdx.x;
    for (int i = t; i < 9216; i += 256) sw[i] = w[i];
    __syncthreads();
    int co = t & 31, xl = t >> 5;
    int x = blockIdx.x*8 + xl;
    int b = blockIdx.y;
    float lmax = 0.f;  // relu >= 0
    if (x < 122) {
        float bv = bias[co];
        for (int y = 0; y < 122; y++) {
            float s = bv;
#pragma unroll
            for (int i = 0; i < 3; i++) {
                const float* row = y3 + (((size_t)b*124 + (y + i))*124 + x)*32;
#pragma unroll
                for (int j = 0; j < 3; j++)
#pragma unroll
                    for (int ci = 0; ci < 32; ci++)
                        s = fmaf(row[j*32 + ci], sw[((i*3 + j)*32 + ci)*32 + co], s);
            }
            lmax = fmaxf(lmax, s);
        }
    }
    // non-negative floats: int-bit compare is order-preserving
    atomicMax((int*)&gm[b*32 + co], __float_as_int(lmax));
}

// ---------------- dense: h[b] = gm[b,:] @ dw + db ----------------
__global__ void dense_k(const float* __restrict__ gm, const float* __restrict__ dw,
                        const float* __restrict__ db, float* __restrict__ h,
                        float* __restrict__ out_tail) {
    int b = threadIdx.x;
    if (b >= B) return;
    float s = db[0];
#pragma unroll
    for (int c = 0; c < 32; c++) s = fmaf(gm[b*32 + c], dw[c], s);
    h[b] = s;
    out_tail[b] = s;
}

// ---------------- marker init: m = xc - h[b] ----------------
__global__ void minit_k(const float* __restrict__ xc, const float* __restrict__ h,
                        float* __restrict__ m) {
    int idx = blockIdx.x*blockDim.x + threadIdx.x;
    int b = idx >> 16;  // H0*W0 == 65536
    m[idx] = xc[idx] - h[b];
}

// ---------------- geodesic reconstruction: 5 fused steps of m = min(dilate3(m), mask) ----------------
#define RK 5
#define RT 32
#define RS (RT + 2*RK)  // 42
__global__ void recon_k(const float* __restrict__ src, const float* __restrict__ mask,
                        float* __restrict__ dst) {
    __shared__ float sm[2][RS*RS];
    __shared__ float sk[RS*RS];
    int t = threadIdx.x;  // 256
    int ox = blockIdx.x*RT - RK;
    int oy = blockIdx.y*RT - RK;
    int b  = blockIdx.z;
    const size_t boff = (size_t)b*H0*W0;
    for (int i = t; i < RS*RS; i += 256) {
        int ly = i / RS, lx = i % RS;
        int gy = oy + ly, gx = ox + lx;
        bool inb = (gy >= 0 && gy < H0 && gx >= 0 && gx < W0);
        sm[0][i] = inb ? src[boff + gy*W0 + gx]  : -CUDART_INF_F;
        sk[i]    = inb ? mask[boff + gy*W0 + gx] : -CUDART_INF_F;
    }
    __syncthreads();
    int cur = 0;
#pragma unroll
    for (int step = 0; step < RK; step++) {
        for (int i = t; i < RS*RS; i += 256) {
            int ly = i / RS, lx = i % RS;
            float v;
            if (ly > 0 && ly < RS-1 && lx > 0 && lx < RS-1) {
                const float* s0 = &sm[cur][i];
                float a = fmaxf(fmaxf(s0[-RS-1], s0[-RS]), s0[-RS+1]);
                float c = fmaxf(fmaxf(s0[-1],    s0[0]),   s0[1]);
                float d = fmaxf(fmaxf(s0[RS-1],  s0[RS]),  s0[RS+1]);
                v = fminf(fmaxf(fmaxf(a, c), d), sk[i]);
            } else {
                v = sm[cur][i];
            }
            sm[1-cur][i] = v;
        }
        __syncthreads();
        cur ^= 1;
    }
    int tx = t & 31, ty = t >> 5;
#pragma unroll
    for (int k = 0; k < 4; k++) {
        int r = ty + 8*k;
        dst[boff + (size_t)(oy + RK + r)*W0 + (ox + RK + tx)] = sm[cur][(r + RK)*RS + (tx + RK)];
    }
}

// ---------------- launch ----------------
extern "C" void kernel_launch(void* const* d_in, const int* in_sizes, int n_in,
                              void* d_out, int out_size) {
    const float* x    = (const float*)d_in[0];
    const float* ko   = (const float*)d_in[1];
    const float* kc   = (const float*)d_in[2];
    const float* w1   = (const float*)d_in[3];
    const float* b1   = (const float*)d_in[4];
    const float* w2   = (const float*)d_in[5];
    const float* b2   = (const float*)d_in[6];
    const float* w3   = (const float*)d_in[7];
    const float* b3   = (const float*)d_in[8];
    const float* w4   = (const float*)d_in[9];
    const float* b4   = (const float*)d_in[10];
    const float* bn1g = (const float*)d_in[11];
    const float* bn1b = (const float*)d_in[12];
    const float* bn1m = (const float*)d_in[13];
    const float* bn1v = (const float*)d_in[14];
    const float* bn2g = (const float*)d_in[15];
    const float* bn2b = (const float*)d_in[16];
    const float* bn2m = (const float*)d_in[17];
    const float* bn2v = (const float*)d_in[18];
    const float* bn3g = (const float*)d_in[19];
    const float* bn3b = (const float*)d_in[20];
    const float* bn3m = (const float*)d_in[21];
    const float* bn3v = (const float*)d_in[22];
    const float* dw   = (const float*)d_in[23];
    const float* db   = (const float*)d_in[24];
    float* out = (float*)d_out;

    float *MA, *MB, *XC, *Y1, *Y2, *Y3, *GM, *HH;
    cudaGetSymbolAddress((void**)&MA, g_MA);
    cudaGetSymbolAddress((void**)&MB, g_MB);
    cudaGetSymbolAddress((void**)&XC, g_XC);
    cudaGetSymbolAddress((void**)&Y1, g_Y1);
    cudaGetSymbolAddress((void**)&Y2, g_Y2);
    cudaGetSymbolAddress((void**)&Y3, g_Y3);
    cudaGetSymbolAddress((void**)&GM, g_GM);
    cudaGetSymbolAddress((void**)&HH, g_H);

    // morphology: xo = dilate(erode(x, ko), ko); xc = erode(dilate(xo, kc), kc)
    morph_k<true ><<<dim3(H0, B), W0>>>(x,  MA, ko);
    morph_k<false><<<dim3(H0, B), W0>>>(MA, MB, ko);
    morph_k<false><<<dim3(H0, B), W0>>>(MB, MA, kc);
    morph_k<true ><<<dim3(H0, B), W0>>>(MA, XC, kc);

    // CNN
    conv1_k<<<dim3(8, 254, B), 256>>>(XC, w1, b1, bn1g, bn1b, bn1m, bn1v, Y1);
    conv2_k<<<dim3(8, 126, B), 256>>>(Y1, w2, b2, bn2g, bn2b, bn2m, bn2v, Y2);
    conv3_k<<<dim3(16, 124, B), 256>>>(Y2, w3, b3, bn3g, bn3b, bn3m, bn3v, Y3);
    cudaMemsetAsync(GM, 0, B*32*sizeof(float));
    conv4_k<<<dim3(16, B), 256>>>(Y3, w4, b4, GM);
    dense_k<<<1, 32>>>(GM, dw, db, HH, out + (size_t)NPIX);

    // h-maxima: 50 steps = 10 launches of 5 fused steps; last writes d_out directly
    minit_k<<<NPIX/256, 256>>>(XC, HH, MA);
    float* bufs[2] = {MA, MB};
    for (int l = 0; l < 10; l++) {
        float* srcp = bufs[l & 1];
        float* dstp = (l == 9) ? out : bufs[(l + 1) & 1];
        recon_k<<<dim3(8, 8, B), 256>>>(srcp, XC, dstp);
    }
}

// round 2
// speedup vs baseline: 3.0227x; 3.0227x over previous
#include <cuda_runtime.h>
#include <math_constants.h>

#define B 32
#define H0 256
#define W0 256
#define NPIX (B*H0*W0)
#define BN_EPS 1e-3f

// ---------------- scratch (global device arrays; no allocation) ----------------
__device__ float g_MA[NPIX];
__device__ float g_MB[NPIX];
__device__ float g_XC[NPIX];
__device__ float g_Y1[(size_t)B*8*254*254];    // conv1 out, channel-first
__device__ float g_YT[(size_t)B*16*252*252];   // conv2 out (pre-pool), channel-first
__device__ float g_Y2[(size_t)B*16*126*126];   // pooled+bn2
__device__ float g_Y3[(size_t)B*32*124*124];   // conv3 out
__device__ float g_GM[B*32];
__device__ float g_H[B];

// ---------------- 3x3 morphology ----------------
template<bool ERO>
__global__ void morph_k(const float* __restrict__ in, float* __restrict__ out,
                        const float* __restrict__ k9) {
    int x = threadIdx.x;
    int y = blockIdx.x;
    int b = blockIdx.y;
    const float* base = in + (size_t)b*H0*W0;
    float best = ERO ? CUDART_INF_F : -CUDART_INF_F;
#pragma unroll
    for (int i = 0; i < 3; i++) {
        int yy = y + i - 1;
        if (yy < 0 || yy >= H0) continue;
#pragma unroll
        for (int j = 0; j < 3; j++) {
            int xx = x + j - 1;
            if (xx < 0 || xx >= W0) continue;
            float v = base[yy*W0 + xx];
            if (ERO) { v -= k9[(2-i)*3 + (2-j)]; best = fminf(best, v); }
            else     { v += k9[i*3 + j];         best = fmaxf(best, v); }
        }
    }
    out[(size_t)b*H0*W0 + y*W0 + x] = best;
}

// ---------------- conv1 (1->8) + relu + bn1, channel-first output ----------------
__global__ void conv1_k(const float* __restrict__ xc, const float* __restrict__ w,
                        const float* __restrict__ bias,
                        const float* __restrict__ gg, const float* __restrict__ bb,
                        const float* __restrict__ mm, const float* __restrict__ vv,
                        float* __restrict__ out) {
    __shared__ float ws[72];
    int t = threadIdx.x;
    if (t < 72) ws[t] = w[t];
    __syncthreads();
    int y = blockIdx.x, b = blockIdx.y;
    int x = t;
    if (x >= 254) return;
    const float* base = xc + ((size_t)b*H0 + y)*W0 + x;
    float acc[8];
#pragma unroll
    for (int k = 0; k < 8; k++) acc[k] = bias[k];
#pragma unroll
    for (int tap = 0; tap < 9; tap++) {
        float v = base[(tap/3)*W0 + (tap%3)];
#pragma unroll
        for (int k = 0; k < 8; k++) acc[k] = fmaf(v, ws[tap*8 + k], acc[k]);
    }
#pragma unroll
    for (int k = 0; k < 8; k++) {
        float sc = gg[k] * rsqrtf(vv[k] + BN_EPS);
        float r = sc * (fmaxf(acc[k], 0.f) - mm[k]) + bb[k];
        out[((size_t)(b*8 + k)*254 + y)*254 + x] = r;
    }
}

// ---------------- generic register-tiled 3x3 conv, channel-first ----------------
// MODE 0: store relu(conv+b)           (conv2)
// MODE 1: store bn(relu(conv+b))       (conv3)
// MODE 2: global max of relu(conv+b)   (conv4; pool dropped since max o pool == max)
template<int CI, int CO, int HIN, int WIN, int MODE>
__global__ __launch_bounds__(256)
void conv_k(const float* __restrict__ gin, const float* __restrict__ gw,
            const float* __restrict__ gb,
            const float* __restrict__ bng, const float* __restrict__ bnb,
            const float* __restrict__ bnm, const float* __restrict__ bnv,
            float* __restrict__ gout) {
    constexpr int WOUT = WIN - 2, HOUT = HIN - 2;
    constexpr int NCOG = CO / 4;             // co groups of 4
    constexpr int ROWW = (NCOG == 8) ? 4 : 8;// spatial slots per tile row
    constexpr int XS   = 32 / ROWW;          // outputs per thread along x (8 or 4)
    constexpr int CC   = (CI > 16) ? 16 : CI;// ci chunk
    constexpr int NCH  = CI / CC;

    __shared__ float in_s[CC*10*36];
    __shared__ float w_s[9*CC*CO];
    __shared__ float smax[CO];

    int tid = threadIdx.x;
    int cog  = tid % NCOG;
    int slot = tid / NCOG;
    int yl = slot / ROWW;
    int xo = (slot % ROWW) * XS;
    int ox0 = blockIdx.x * 32, oy0 = blockIdx.y * 8;
    int b = blockIdx.z;

    float acc[XS][4];
#pragma unroll
    for (int m = 0; m < XS; m++)
#pragma unroll
        for (int k = 0; k < 4; k++) acc[m][k] = 0.f;
    if (MODE == 2 && tid < CO) smax[tid] = 0.f;

    for (int cc = 0; cc < NCH; cc++) {
        __syncthreads();
        // input tile: CC x 10 x 34 (row stride 36)
        for (int idx = tid; idx < CC*340; idx += 256) {
            int ci = idx / 340, rem = idx % 340;
            int yy = rem / 34, xx = rem % 34;
            int gy = oy0 + yy, gx = ox0 + xx;
            float v = 0.f;
            if (gy < HIN && gx < WIN)
                v = gin[((size_t)(b*CI + cc*CC + ci)*HIN + gy)*WIN + gx];
            in_s[ci*360 + yy*36 + xx] = v;
        }
        // weights chunk: same [tap][ci][co] layout as global HWIO
        for (int idx = tid; idx < 9*CC*CO; idx += 256) {
            int tap = idx / (CC*CO), r = idx - tap*(CC*CO);
            w_s[idx] = gw[tap*(CI*CO) + cc*(CC*CO) + r];
        }
        __syncthreads();
#pragma unroll
        for (int tap = 0; tap < 9; tap++) {
            const int dy = tap/3, dx = tap%3;
            const float* ip0 = in_s + (yl+dy)*36 + xo + dx;
            const float* wp  = w_s + tap*CC*CO + cog*4;
#pragma unroll 4
            for (int ci = 0; ci < CC; ci++) {
                float4 w4 = *(const float4*)wp;
                const float* ip = ip0 + ci*360;
#pragma unroll
                for (int m = 0; m < XS; m++) {
                    float v = ip[m];
                    acc[m][0] = fmaf(v, w4.x, acc[m][0]);
                    acc[m][1] = fmaf(v, w4.y, acc[m][1]);
                    acc[m][2] = fmaf(v, w4.z, acc[m][2]);
                    acc[m][3] = fmaf(v, w4.w, acc[m][3]);
                }
                wp += CO;
            }
        }
    }

    // epilogue
    int oy = oy0 + yl;
    float bia[4];
#pragma unroll
    for (int k = 0; k < 4; k++) bia[k] = gb[cog*4 + k];

    if (MODE == 2) {
        float lm[4] = {0.f, 0.f, 0.f, 0.f};  // relu floor
        if (oy < HOUT) {
#pragma unroll
            for (int m = 0; m < XS; m++) {
                if (ox0 + xo + m < WOUT) {
#pragma unroll
                    for (int k = 0; k < 4; k++)
                        lm[k] = fmaxf(lm[k], acc[m][k] + bia[k]);
                }
            }
        }
#pragma unroll
        for (int k = 0; k < 4; k++)
            atomicMax((int*)&smax[cog*4 + k], __float_as_int(lm[k]));
        __syncthreads();
        if (tid < CO)
            atomicMax((int*)&gout[b*CO + tid], __float_as_int(smax[tid]));
    } else {
        float sc[4], sb[4], sm_[4];
        if (MODE == 1) {
#pragma unroll
            for (int k = 0; k < 4; k++) {
                int co = cog*4 + k;
                sc[k] = bng[co] * rsqrtf(bnv[co] + BN_EPS);
                sb[k] = bnb[co];
                sm_[k] = bnm[co];
            }
        }
        if (oy < HOUT) {
#pragma unroll
            for (int m = 0; m < XS; m++) {
                int ox = ox0 + xo + m;
                if (ox < WOUT) {
#pragma unroll
                    for (int k = 0; k < 4; k++) {
                        float v = fmaxf(acc[m][k] + bia[k], 0.f);
                        if (MODE == 1) v = sc[k]*(v - sm_[k]) + sb[k];
                        gout[((size_t)(b*CO + cog*4 + k)*HOUT + oy)*WOUT + ox] = v;
                    }
                }
            }
        }
    }
}

// ---------------- maxpool 2x2 + bn2 ----------------
__global__ void poolbn_k(const float* __restrict__ in,
                         const float* __restrict__ gg, const float* __restrict__ bb,
                         const float* __restrict__ mm, const float* __restrict__ vv,
                         float* __restrict__ out) {
    int idx = blockIdx.x*256 + threadIdx.x;
    if (idx >= B*16*126*126) return;
    int q = idx % 126, t1 = idx / 126;
    int p = t1 % 126, t2 = t1 / 126;
    int c = t2 % 16, b = t2 / 16;
    const float* base = in + ((size_t)(b*16 + c)*252 + 2*p)*252 + 2*q;
    float mx = fmaxf(fmaxf(base[0], base[1]), fmaxf(base[252], base[253]));
    float sc = gg[c] * rsqrtf(vv[c] + BN_EPS);
    out[idx] = sc * (mx - mm[c]) + bb[c];
}

// ---------------- dense ----------------
__global__ void dense_k(const float* __restrict__ gm, const float* __restrict__ dw,
                        const float* __restrict__ db, float* __restrict__ h,
                        float* __restrict__ out_tail) {
    int b = threadIdx.x;
    if (b >= B) return;
    float s = db[0];
#pragma unroll
    for (int c = 0; c < 32; c++) s = fmaf(gm[b*32 + c], dw[c], s);
    h[b] = s;
    out_tail[b] = s;
}

// ---------------- marker init: m = xc - h[b] ----------------
__global__ void minit_k(const float* __restrict__ xc, const float* __restrict__ h,
                        float* __restrict__ m) {
    int idx = blockIdx.x*blockDim.x + threadIdx.x;
    int b = idx >> 16;  // H0*W0 == 65536
    m[idx] = xc[idx] - h[b];
}

// ---------------- geodesic reconstruction: 5 fused steps, 64x64 tile ----------------
#define RK 5
#define RT 64
#define RS (RT + 2*RK)          // 74
#define RCELL (RS*RS)           // 5476
#define RNIT ((RCELL + 255)/256)// 22
__global__ __launch_bounds__(256)
void recon_k(const float* __restrict__ src, const float* __restrict__ mask,
             float* __restrict__ dst) {
    __shared__ float sm[2][RCELL];
    int t = threadIdx.x;
    int ox = blockIdx.x*RT - RK;
    int oy = blockIdx.y*RT - RK;
    const size_t boff = (size_t)blockIdx.z*H0*W0;

    float mk[RNIT];
    bool  inter[RNIT];
#pragma unroll
    for (int k = 0; k < RNIT; k++) {
        int i = t + k*256;
        float sv = -CUDART_INF_F, mv = -CUDART_INF_F;
        bool it = false;
        if (i < RCELL) {
            int ly = i / RS, lx = i % RS;
            int gy = oy + ly, gx = ox + lx;
            if (gy >= 0 && gy < H0 && gx >= 0 && gx < W0) {
                sv = src[boff + gy*W0 + gx];
                mv = mask[boff + gy*W0 + gx];
            }
            sm[0][i] = sv;
            it = (ly > 0 && ly < RS-1 && lx > 0 && lx < RS-1);
        }
        mk[k] = mv;
        inter[k] = it;
    }
    __syncthreads();
    int cur = 0;
#pragma unroll
    for (int step = 0; step < RK; step++) {
#pragma unroll
        for (int k = 0; k < RNIT; k++) {
            int i = t + k*256;
            if (i < RCELL) {
                float v;
                if (inter[k]) {
                    const float* s0 = &sm[cur][i];
                    float a = fmaxf(fmaxf(s0[-RS-1], s0[-RS]), s0[-RS+1]);
                    float c = fmaxf(fmaxf(s0[-1],    s0[0]),   s0[1]);
                    float d = fmaxf(fmaxf(s0[RS-1],  s0[RS]),  s0[RS+1]);
                    v = fminf(fmaxf(fmaxf(a, c), d), mk[k]);
                } else {
                    v = sm[cur][i];
                }
                sm[1-cur][i] = v;
            }
        }
        __syncthreads();
        cur ^= 1;
    }
    int tx = t & 63, tyq = t >> 6;
#pragma unroll
    for (int k = 0; k < 16; k++) {
        int r = tyq + 4*k;
        dst[boff + (size_t)(oy + RK + r)*W0 + (ox + RK + tx)] =
            sm[cur][(r + RK)*RS + (tx + RK)];
    }
}

// ---------------- launch ----------------
extern "C" void kernel_launch(void* const* d_in, const int* in_sizes, int n_in,
                              void* d_out, int out_size) {
    const float* x    = (const float*)d_in[0];
    const float* ko   = (const float*)d_in[1];
    const float* kc   = (const float*)d_in[2];
    const float* w1   = (const float*)d_in[3];
    const float* b1   = (const float*)d_in[4];
    const float* w2   = (const float*)d_in[5];
    const float* b2   = (const float*)d_in[6];
    const float* w3   = (const float*)d_in[7];
    const float* b3   = (const float*)d_in[8];
    const float* w4   = (const float*)d_in[9];
    const float* b4   = (const float*)d_in[10];
    const float* bn1g = (const float*)d_in[11];
    const float* bn1b = (const float*)d_in[12];
    const float* bn1m = (const float*)d_in[13];
    const float* bn1v = (const float*)d_in[14];
    const float* bn2g = (const float*)d_in[15];
    const float* bn2b = (const float*)d_in[16];
    const float* bn2m = (const float*)d_in[17];
    const float* bn2v = (const float*)d_in[18];
    const float* bn3g = (const float*)d_in[19];
    const float* bn3b = (const float*)d_in[20];
    const float* bn3m = (const float*)d_in[21];
    const float* bn3v = (const float*)d_in[22];
    const float* dw   = (const float*)d_in[23];
    const float* db   = (const float*)d_in[24];
    float* out = (float*)d_out;

    float *MA, *MB, *XC, *Y1, *YT, *Y2, *Y3, *GM, *HH;
    cudaGetSymbolAddress((void**)&MA, g_MA);
    cudaGetSymbolAddress((void**)&MB, g_MB);
    cudaGetSymbolAddress((void**)&XC, g_XC);
    cudaGetSymbolAddress((void**)&Y1, g_Y1);
    cudaGetSymbolAddress((void**)&YT, g_YT);
    cudaGetSymbolAddress((void**)&Y2, g_Y2);
    cudaGetSymbolAddress((void**)&Y3, g_Y3);
    cudaGetSymbolAddress((void**)&GM, g_GM);
    cudaGetSymbolAddress((void**)&HH, g_H);

    // morphology: xo = dilate(erode(x, ko), ko); xc = erode(dilate(xo, kc), kc)
    morph_k<true ><<<dim3(H0, B), W0>>>(x,  MA, ko);
    morph_k<false><<<dim3(H0, B), W0>>>(MA, MB, ko);
    morph_k<false><<<dim3(H0, B), W0>>>(MB, MA, kc);
    morph_k<true ><<<dim3(H0, B), W0>>>(MA, XC, kc);

    // CNN (channel-first intermediates)
    conv1_k<<<dim3(254, B), 256>>>(XC, w1, b1, bn1g, bn1b, bn1m, bn1v, Y1);
    conv_k<8, 16, 254, 254, 0><<<dim3(8, 32, B), 256>>>(
        Y1, w2, b2, nullptr, nullptr, nullptr, nullptr, YT);
    poolbn_k<<<(B*16*126*126 + 255)/256, 256>>>(YT, bn2g, bn2b, bn2m, bn2v, Y2);
    conv_k<16, 32, 126, 126, 1><<<dim3(4, 16, B), 256>>>(
        Y2, w3, b3, bn3g, bn3b, bn3m, bn3v, Y3);
    cudaMemsetAsync(GM, 0, B*32*sizeof(float));
    conv_k<32, 32, 124, 124, 2><<<dim3(4, 16, B), 256>>>(
        Y3, w4, b4, nullptr, nullptr, nullptr, nullptr, GM);
    dense_k<<<1, 32>>>(GM, dw, db, HH, out + (size_t)NPIX);

    // h-maxima: 50 steps = 10 launches of 5 fused steps; last writes d_out
    minit_k<<<NPIX/256, 256>>>(XC, HH, MA);
    float* bufs[2] = {MA, MB};
    for (int l = 0; l < 10; l++) {
        float* srcp = bufs[l & 1];
        float* dstp = (l == 9) ? out : bufs[(l + 1) & 1];
        recon_k<<<dim3(4, 4, B), 256>>>(srcp, XC, dstp);
    }
}

// round 3
// speedup vs baseline: 3.3691x; 1.1146x over previous
#include <cuda_runtime.h>
#include <math_constants.h>

#define B 32
#define H0 256
#define W0 256
#define NPIX (B*H0*W0)
#define BN_EPS 1e-3f

typedef unsigned long long u64t;

__device__ __forceinline__ u64t pk2(float a, float b) {
    u64t r; asm("mov.b64 %0,{%1,%2};" : "=l"(r) : "f"(a), "f"(b)); return r;
}
__device__ __forceinline__ void upk2(u64t v, float& a, float& b) {
    asm("mov.b64 {%0,%1},%2;" : "=f"(a), "=f"(b) : "l"(v));
}
__device__ __forceinline__ void fma2(u64t& d, u64t a, u64t b) {
    asm("fma.rn.f32x2 %0,%1,%2,%0;" : "+l"(d) : "l"(a), "l"(b));
}

// ---------------- scratch ----------------
__device__ float g_MA[NPIX];
__device__ float g_MB[NPIX];
__device__ float g_XC[NPIX];
__device__ float g_Y1[(size_t)B*8*254*254];
__device__ float g_Y2[(size_t)B*16*126*126];
__device__ float g_Y3[(size_t)B*32*124*124];
__device__ float g_GM[B*32];
__device__ float g_H[B];

// ---------------- fused 4-pass morphology: E(ko),D(ko),D(kc),E(kc), halo 4 ----------------
#define MT 64
#define MHL 4
#define MS (MT + 2*MHL)      // 72
#define MCELL (MS*MS)        // 5184
#define MNIT ((MCELL + 255)/256)  // 21
__global__ __launch_bounds__(256)
void morph4_k(const float* __restrict__ x, float* __restrict__ xc,
              const float* __restrict__ ko, const float* __restrict__ kc) {
    __shared__ float sm[2][MCELL];
    __shared__ float sk[18];
    int t = threadIdx.x;
    if (t < 18) sk[t] = (t < 9) ? ko[t] : kc[t - 9];
    int ox = blockIdx.x*MT - MHL;
    int oy = blockIdx.y*MT - MHL;
    const size_t boff = (size_t)blockIdx.z*H0*W0;

    bool inb[MNIT], inter[MNIT];
#pragma unroll
    for (int k = 0; k < MNIT; k++) {
        int i = t + k*256;
        bool ib = false, it = false;
        if (i < MCELL) {
            int ly = i / MS, lx = i % MS;
            int gy = oy + ly, gx = ox + lx;
            ib = (gy >= 0 && gy < H0 && gx >= 0 && gx < W0);
            sm[0][i] = ib ? x[boff + gy*W0 + gx] : CUDART_INF_F;  // pad for op0=E
            it = (ly > 0 && ly < MS-1 && lx > 0 && lx < MS-1);
        }
        inb[k] = ib; inter[k] = it;
    }
    __syncthreads();
    // op: 0=E(ko) 1=D(ko) 2=D(kc) 3=E(kc)
    int cur = 0;
#pragma unroll
    for (int op = 0; op < 4; op++) {
        const bool ero = (op == 0 || op == 3);
        const int koff = (op < 2) ? 0 : 9;
        // pad value outside image for NEXT op (op+1): ops 1,2 are D -> -inf; op3 is E -> +inf
        const float nextpad = (op >= 2) ? CUDART_INF_F : -CUDART_INF_F;
#pragma unroll
        for (int k = 0; k < MNIT; k++) {
            int i = t + k*256;
            if (i < MCELL) {
                float v;
                if (!inb[k]) {
                    v = nextpad;
                } else if (inter[k]) {
                    const float* s0 = &sm[cur][i];
                    if (ero) {
                        float m = s0[-MS-1] - sk[koff + 8];
                        m = fminf(m, s0[-MS  ] - sk[koff + 7]);
                        m = fminf(m, s0[-MS+1] - sk[koff + 6]);
                        m = fminf(m, s0[-1]    - sk[koff + 5]);
                        m = fminf(m, s0[0]     - sk[koff + 4]);
                        m = fminf(m, s0[1]     - sk[koff + 3]);
                        m = fminf(m, s0[MS-1]  - sk[koff + 2]);
                        m = fminf(m, s0[MS  ]  - sk[koff + 1]);
                        m = fminf(m, s0[MS+1]  - sk[koff + 0]);
                        v = m;
                    } else {
                        float m = s0[-MS-1] + sk[koff + 0];
                        m = fmaxf(m, s0[-MS  ] + sk[koff + 1]);
                        m = fmaxf(m, s0[-MS+1] + sk[koff + 2]);
                        m = fmaxf(m, s0[-1]    + sk[koff + 3]);
                        m = fmaxf(m, s0[0]     + sk[koff + 4]);
                        m = fmaxf(m, s0[1]     + sk[koff + 5]);
                        m = fmaxf(m, s0[MS-1]  + sk[koff + 6]);
                        m = fmaxf(m, s0[MS  ]  + sk[koff + 7]);
                        m = fmaxf(m, s0[MS+1]  + sk[koff + 8]);
                        v = m;
                    }
                } else {
                    v = sm[cur][i];
                }
                sm[1-cur][i] = v;
            }
        }
        __syncthreads();
        cur ^= 1;
    }
    int tx = t & 63, tyq = t >> 6;
#pragma unroll
    for (int k = 0; k < 16; k++) {
        int r = tyq + 4*k;
        xc[boff + (size_t)(oy + MHL + r)*W0 + (ox + MHL + tx)] =
            sm[cur][(r + MHL)*MS + (tx + MHL)];
    }
}

// ---------------- conv1 (1->8) + relu + bn1, channel-first, packed FMA ----------------
__global__ void conv1_k(const float* __restrict__ xc, const float* __restrict__ w,
                        const float* __restrict__ bias,
                        const float* __restrict__ gg, const float* __restrict__ bb,
                        const float* __restrict__ mm, const float* __restrict__ vv,
                        float* __restrict__ out) {
    __shared__ float ws[72];
    int t = threadIdx.x;
    if (t < 72) ws[t] = w[t];
    __syncthreads();
    int y = blockIdx.x, b = blockIdx.y;
    int x = t;
    if (x >= 254) return;
    const float* base = xc + ((size_t)b*H0 + y)*W0 + x;
    u64t acc[4];
#pragma unroll
    for (int p = 0; p < 4; p++) acc[p] = pk2(bias[2*p], bias[2*p+1]);
#pragma unroll
    for (int tap = 0; tap < 9; tap++) {
        float v = base[(tap/3)*W0 + (tap%3)];
        u64t pv = pk2(v, v);
        const u64t* wq = (const u64t*)(ws + tap*8);
#pragma unroll
        for (int p = 0; p < 4; p++) fma2(acc[p], pv, wq[p]);
    }
#pragma unroll
    for (int p = 0; p < 4; p++) {
        float a0, a1; upk2(acc[p], a0, a1);
        int k0 = 2*p, k1 = 2*p+1;
        float s0 = gg[k0] * rsqrtf(vv[k0] + BN_EPS);
        float s1 = gg[k1] * rsqrtf(vv[k1] + BN_EPS);
        out[((size_t)(b*8 + k0)*254 + y)*254 + x] = s0*(fmaxf(a0,0.f) - mm[k0]) + bb[k0];
        out[((size_t)(b*8 + k1)*254 + y)*254 + x] = s1*(fmaxf(a1,0.f) - mm[k1]) + bb[k1];
    }
}

// ---------------- register-tiled 3x3 conv, packed f32x2 FMA, channel-first ----------------
// MODE 1: store bn(relu(conv+b))                     (conv3)
// MODE 2: global max of relu(conv+b)                 (conv4; pool dropped)
// MODE 3: store bn(maxpool2(relu(conv+b)))           (conv2, fused pool)
template<int CI, int CO, int HIN, int WIN, int TW, int MODE>
__global__ __launch_bounds__(256)
void conv_k(const float* __restrict__ gin, const float* __restrict__ gw,
            const float* __restrict__ gb,
            const float* __restrict__ bng, const float* __restrict__ bnb,
            const float* __restrict__ bnm, const float* __restrict__ bnv,
            float* __restrict__ gout) {
    constexpr int WOUT = WIN - 2, HOUT = HIN - 2;
    constexpr int NCOG = CO / 8;          // co-groups of 8 per thread
    constexpr int SPR  = TW / 4;          // slots per row (XS = 4)
    constexpr int CC   = (CI > 16) ? 16 : CI;
    constexpr int NCH  = CI / CC;
    constexpr int STR  = TW + 4;
    constexpr int LW   = TW + 2;          // loaded width

    __shared__ float in_s[CC*10*STR];
    __shared__ float w_s[9*CC*CO];
    __shared__ float smax[(MODE == 2) ? CO : 1];
    __shared__ float xpool_s[(MODE == 3) ? 2048 : 1];

    int tid = threadIdx.x;
    int cog  = tid % NCOG;
    int slot = tid / NCOG;
    int yl = slot / SPR;
    int xo = (slot % SPR) * 4;
    int ox0 = blockIdx.x * TW, oy0 = blockIdx.y * 8;
    int b = blockIdx.z;

    u64t acc[4][4];
#pragma unroll
    for (int m = 0; m < 4; m++)
#pragma unroll
        for (int p = 0; p < 4; p++) acc[m][p] = 0ull;
    if (MODE == 2 && tid < CO) smax[tid] = 0.f;

    for (int cc = 0; cc < NCH; cc++) {
        __syncthreads();
        for (int idx = tid; idx < CC*10*LW; idx += 256) {
            int ci = idx / (10*LW), rem = idx % (10*LW);
            int yy = rem / LW, xx = rem % LW;
            int gy = oy0 + yy, gx = ox0 + xx;
            float v = 0.f;
            if (gy < HIN && gx < WIN)
                v = gin[((size_t)(b*CI + cc*CC + ci)*HIN + gy)*WIN + gx];
            in_s[ci*(10*STR) + yy*STR + xx] = v;
        }
        for (int idx = tid; idx < 9*CC*CO; idx += 256) {
            int tap = idx / (CC*CO), r = idx - tap*(CC*CO);
            w_s[idx] = gw[tap*(CI*CO) + cc*(CC*CO) + r];
        }
        __syncthreads();
#pragma unroll
        for (int tap = 0; tap < 9; tap++) {
            const int dy = tap/3, dx = tap%3;
            const float* ip0 = in_s + (yl+dy)*STR + xo + dx;
            const float* wp0 = w_s + tap*CC*CO + cog*8;
#pragma unroll 2
            for (int ci = 0; ci < CC; ci++) {
                const u64t* wq = (const u64t*)(wp0 + ci*CO);
                u64t w0 = wq[0], w1 = wq[1], w2 = wq[2], w3 = wq[3];
                const float* ip = ip0 + ci*(10*STR);
#pragma unroll
                for (int m = 0; m < 4; m++) {
                    float v = ip[m];
                    u64t pv = pk2(v, v);
                    fma2(acc[m][0], pv, w0);
                    fma2(acc[m][1], pv, w1);
                    fma2(acc[m][2], pv, w2);
                    fma2(acc[m][3], pv, w3);
                }
            }
        }
    }

    // unpack + bias + relu
    float r[4][8];
    float bia[8];
#pragma unroll
    for (int k = 0; k < 8; k++) bia[k] = gb[cog*8 + k];
#pragma unroll
    for (int m = 0; m < 4; m++)
#pragma unroll
        for (int p = 0; p < 4; p++) {
            float a0, a1; upk2(acc[m][p], a0, a1);
            r[m][2*p]   = fmaxf(a0 + bia[2*p],   0.f);
            r[m][2*p+1] = fmaxf(a1 + bia[2*p+1], 0.f);
        }

    int oy = oy0 + yl;

    if (MODE == 2) {
        float lm[8];
#pragma unroll
        for (int k = 0; k < 8; k++) lm[k] = 0.f;
        if (oy < HOUT) {
#pragma unroll
            for (int m = 0; m < 4; m++)
                if (ox0 + xo + m < WOUT)
#pragma unroll
                    for (int k = 0; k < 8; k++) lm[k] = fmaxf(lm[k], r[m][k]);
        }
#pragma unroll
        for (int k = 0; k < 8; k++)
            atomicMax((int*)&smax[cog*8 + k], __float_as_int(lm[k]));
        __syncthreads();
        if (tid < CO)
            atomicMax((int*)&gout[b*CO + tid], __float_as_int(smax[tid]));
    } else if (MODE == 3) {
        // x-pool in registers: pairs (0,1) and (2,3)
        float xp[2][8];
#pragma unroll
        for (int q = 0; q < 2; q++)
#pragma unroll
            for (int k = 0; k < 8; k++)
                xp[q][k] = fmaxf(r[2*q][k], r[2*q+1][k]);
        int py = yl >> 1;
        int pxb = xo >> 1;
        if (yl & 1) {
#pragma unroll
            for (int q = 0; q < 2; q++)
#pragma unroll
                for (int k = 0; k < 8; k++)
                    xpool_s[((py*32 + pxb + q)*16) + cog*8 + k] = xp[q][k];
        }
        __syncthreads();
        if (!(yl & 1)) {
            int gy_p = (oy0 + yl) >> 1;
            if (gy_p < HOUT/2) {
#pragma unroll
                for (int q = 0; q < 2; q++) {
                    int gx_p = ((ox0 + xo) >> 1) + q;
                    if (gx_p < WOUT/2) {
#pragma unroll
                        for (int k = 0; k < 8; k++) {
                            int co = cog*8 + k;
                            float v = fmaxf(xp[q][k],
                                xpool_s[((py*32 + pxb + q)*16) + co]);
                            float sc = bng[co] * rsqrtf(bnv[co] + BN_EPS);
                            v = sc*(v - bnm[co]) + bnb[co];
                            gout[((size_t)(b*CO + co)*(HOUT/2) + gy_p)*(WOUT/2) + gx_p] = v;
                        }
                    }
                }
            }
        }
    } else {  // MODE 1
        if (oy < HOUT) {
            float sc[8], sb[8], sm_[8];
#pragma unroll
            for (int k = 0; k < 8; k++) {
                int co = cog*8 + k;
                sc[k] = bng[co] * rsqrtf(bnv[co] + BN_EPS);
                sb[k] = bnb[co];
                sm_[k] = bnm[co];
            }
#pragma unroll
            for (int m = 0; m < 4; m++) {
                int ox = ox0 + xo + m;
                if (ox < WOUT) {
#pragma unroll
                    for (int k = 0; k < 8; k++) {
                        float v = sc[k]*(r[m][k] - sm_[k]) + sb[k];
                        gout[((size_t)(b*CO + cog*8 + k)*HOUT + oy)*WOUT + ox] = v;
                    }
                }
            }
        }
    }
}

// ---------------- dense ----------------
__global__ void dense_k(const float* __restrict__ gm, const float* __restrict__ dw,
                        const float* __restrict__ db, float* __restrict__ h,
                        float* __restrict__ out_tail) {
    int b = threadIdx.x;
    if (b >= B) return;
    float s = db[0];
#pragma unroll
    for (int c = 0; c < 32; c++) s = fmaf(gm[b*32 + c], dw[c], s);
    h[b] = s;
    out_tail[b] = s;
}

// ---------------- geodesic reconstruction: 5 fused steps, 64x64 tile ----------------
#define RK 5
#define RT 64
#define RS (RT + 2*RK)
#define RCELL (RS*RS)
#define RNIT ((RCELL + 255)/256)
template<bool INIT>
__global__ __launch_bounds__(256)
void recon_k(const float* __restrict__ src, const float* __restrict__ mask,
             const float* __restrict__ h, float* __restrict__ dst) {
    __shared__ float sm[2][RCELL];
    int t = threadIdx.x;
    int ox = blockIdx.x*RT - RK;
    int oy = blockIdx.y*RT - RK;
    const size_t boff = (size_t)blockIdx.z*H0*W0;
    const float hv = INIT ? h[blockIdx.z] : 0.f;

    float mk[RNIT];
    bool  inter[RNIT];
#pragma unroll
    for (int k = 0; k < RNIT; k++) {
        int i = t + k*256;
        float sv = -CUDART_INF_F, mv = -CUDART_INF_F;
        bool it = false;
        if (i < RCELL) {
            int ly = i / RS, lx = i % RS;
            int gy = oy + ly, gx = ox + lx;
            if (gy >= 0 && gy < H0 && gx >= 0 && gx < W0) {
                mv = mask[boff + gy*W0 + gx];
                sv = INIT ? (mv - hv) : src[boff + gy*W0 + gx];
            }
            sm[0][i] = sv;
            it = (ly > 0 && ly < RS-1 && lx > 0 && lx < RS-1);
        }
        mk[k] = mv;
        inter[k] = it;
    }
    __syncthreads();
    int cur = 0;
#pragma unroll
    for (int step = 0; step < RK; step++) {
#pragma unroll
        for (int k = 0; k < RNIT; k++) {
            int i = t + k*256;
            if (i < RCELL) {
                float v;
                if (inter[k]) {
                    const float* s0 = &sm[cur][i];
                    float a = fmaxf(fmaxf(s0[-RS-1], s0[-RS]), s0[-RS+1]);
                    float c = fmaxf(fmaxf(s0[-1],    s0[0]),   s0[1]);
                    float d = fmaxf(fmaxf(s0[RS-1],  s0[RS]),  s0[RS+1]);
                    v = fminf(fmaxf(fmaxf(a, c), d), mk[k]);
                } else {
                    v = sm[cur][i];
                }
                sm[1-cur][i] = v;
            }
        }
        __syncthreads();
        cur ^= 1;
    }
    int tx = t & 63, tyq = t >> 6;
#pragma unroll
    for (int k = 0; k < 16; k++) {
        int r = tyq + 4*k;
        dst[boff + (size_t)(oy + RK + r)*W0 + (ox + RK + tx)] =
            sm[cur][(r + RK)*RS + (tx + RK)];
    }
}

// ---------------- launch ----------------
extern "C" void kernel_launch(void* const* d_in, const int* in_sizes, int n_in,
                              void* d_out, int out_size) {
    const float* x    = (const float*)d_in[0];
    const float* ko   = (const float*)d_in[1];
    const float* kc   = (const float*)d_in[2];
    const float* w1   = (const float*)d_in[3];
    const float* b1   = (const float*)d_in[4];
    const float* w2   = (const float*)d_in[5];
    const float* b2   = (const float*)d_in[6];
    const float* w3   = (const float*)d_in[7];
    const float* b3   = (const float*)d_in[8];
    const float* w4   = (const float*)d_in[9];
    const float* b4   = (const float*)d_in[10];
    const float* bn1g = (const float*)d_in[11];
    const float* bn1b = (const float*)d_in[12];
    const float* bn1m = (const float*)d_in[13];
    const float* bn1v = (const float*)d_in[14];
    const float* bn2g = (const float*)d_in[15];
    const float* bn2b = (const float*)d_in[16];
    const float* bn2m = (const float*)d_in[17];
    const float* bn2v = (const float*)d_in[18];
    const float* bn3g = (const float*)d_in[19];
    const float* bn3b = (const float*)d_in[20];
    const float* bn3m = (const float*)d_in[21];
    const float* bn3v = (const float*)d_in[22];
    const float* dw   = (const float*)d_in[23];
    const float* db   = (const float*)d_in[24];
    float* out = (float*)d_out;

    float *MA, *MB, *XC, *Y1, *Y2, *Y3, *GM, *HH;
    cudaGetSymbolAddress((void**)&MA, g_MA);
    cudaGetSymbolAddress((void**)&MB, g_MB);
    cudaGetSymbolAddress((void**)&XC, g_XC);
    cudaGetSymbolAddress((void**)&Y1, g_Y1);
    cudaGetSymbolAddress((void**)&Y2, g_Y2);
    cudaGetSymbolAddress((void**)&Y3, g_Y3);
    cudaGetSymbolAddress((void**)&GM, g_GM);
    cudaGetSymbolAddress((void**)&HH, g_H);

    // fused morphology -> XC
    morph4_k<<<dim3(4, 4, B), 256>>>(x, XC, ko, kc);

    // CNN (channel-first intermediates)
    conv1_k<<<dim3(254, B), 256>>>(XC, w1, b1, bn1g, bn1b, bn1m, bn1v, Y1);
    conv_k<8, 16, 254, 254, 64, 3><<<dim3(4, 32, B), 256>>>(
        Y1, w2, b2, bn2g, bn2b, bn2m, bn2v, Y2);
    conv_k<16, 32, 126, 126, 32, 1><<<dim3(4, 16, B), 256>>>(
        Y2, w3, b3, bn3g, bn3b, bn3m, bn3v, Y3);
    cudaMemsetAsync(GM, 0, B*32*sizeof(float));
    conv_k<32, 32, 124, 124, 32, 2><<<dim3(4, 16, B), 256>>>(
        Y3, w4, b4, nullptr, nullptr, nullptr, nullptr, GM);
    dense_k<<<1, 32>>>(GM, dw, db, HH, out + (size_t)NPIX);

    // h-maxima: 50 steps = 10 launches of 5 fused steps (first fuses marker init)
    recon_k<true><<<dim3(4, 4, B), 256>>>(XC, XC, HH, MB);
    float* bufs[2] = {MA, MB};
    for (int l = 1; l < 10; l++) {
        float* srcp = (l & 1) ? MB : MA;
        float* dstp = (l == 9) ? out : ((l & 1) ? MA : MB);
        recon_k<false><<<dim3(4, 4, B), 256>>>(srcp, XC, nullptr, dstp);
    }
    (void)bufs;
}

// round 4
// speedup vs baseline: 3.5230x; 1.0457x over previous
#include <cuda_runtime.h>
#include <math_constants.h>

#define B 32
#define H0 256
#define W0 256
#define NPIX (B*H0*W0)
#define BN_EPS 1e-3f

typedef unsigned long long u64t;

__device__ __forceinline__ u64t pk2(float a, float b) {
    u64t r; asm("mov.b64 %0,{%1,%2};" : "=l"(r) : "f"(a), "f"(b)); return r;
}
__device__ __forceinline__ void upk2(u64t v, float& a, float& b) {
    asm("mov.b64 {%0,%1},%2;" : "=f"(a), "=f"(b) : "l"(v));
}
__device__ __forceinline__ void fma2(u64t& d, u64t a, u64t b) {
    asm("fma.rn.f32x2 %0,%1,%2,%0;" : "+l"(d) : "l"(a), "l"(b));
}

// ---------------- scratch ----------------
__device__ float g_MA[NPIX];
__device__ float g_MB[NPIX];
__device__ float g_XC[NPIX];
__device__ float g_Y1[(size_t)B*8*254*254];
__device__ float g_Y2[(size_t)B*16*126*126];
__device__ float g_Y3[(size_t)B*32*124*124];
__device__ float g_GM[B*32];
__device__ float g_H[B];

// ---------------- fused 4-pass morphology: E(ko),D(ko),D(kc),E(kc), halo 4 ----------------
#define MT 64
#define MHL 4
#define MS (MT + 2*MHL)
#define MCELL (MS*MS)
#define MNIT ((MCELL + 255)/256)
__global__ __launch_bounds__(256)
void morph4_k(const float* __restrict__ x, float* __restrict__ xc,
              const float* __restrict__ ko, const float* __restrict__ kc) {
    __shared__ float sm[2][MCELL];
    __shared__ float sk[18];
    int t = threadIdx.x;
    if (t < 18) sk[t] = (t < 9) ? ko[t] : kc[t - 9];
    int ox = blockIdx.x*MT - MHL;
    int oy = blockIdx.y*MT - MHL;
    const size_t boff = (size_t)blockIdx.z*H0*W0;

    bool inb[MNIT], inter[MNIT];
#pragma unroll
    for (int k = 0; k < MNIT; k++) {
        int i = t + k*256;
        bool ib = false, it = false;
        if (i < MCELL) {
            int ly = i / MS, lx = i % MS;
            int gy = oy + ly, gx = ox + lx;
            ib = (gy >= 0 && gy < H0 && gx >= 0 && gx < W0);
            sm[0][i] = ib ? x[boff + gy*W0 + gx] : CUDART_INF_F;
            it = (ly > 0 && ly < MS-1 && lx > 0 && lx < MS-1);
        }
        inb[k] = ib; inter[k] = it;
    }
    __syncthreads();
    int cur = 0;
#pragma unroll
    for (int op = 0; op < 4; op++) {
        const bool ero = (op == 0 || op == 3);
        const int koff = (op < 2) ? 0 : 9;
        const float nextpad = (op >= 2) ? CUDART_INF_F : -CUDART_INF_F;
#pragma unroll
        for (int k = 0; k < MNIT; k++) {
            int i = t + k*256;
            if (i < MCELL) {
                float v;
                if (!inb[k]) {
                    v = nextpad;
                } else if (inter[k]) {
                    const float* s0 = &sm[cur][i];
                    if (ero) {
                        float m = s0[-MS-1] - sk[koff + 8];
                        m = fminf(m, s0[-MS  ] - sk[koff + 7]);
                        m = fminf(m, s0[-MS+1] - sk[koff + 6]);
                        m = fminf(m, s0[-1]    - sk[koff + 5]);
                        m = fminf(m, s0[0]     - sk[koff + 4]);
                        m = fminf(m, s0[1]     - sk[koff + 3]);
                        m = fminf(m, s0[MS-1]  - sk[koff + 2]);
                        m = fminf(m, s0[MS  ]  - sk[koff + 1]);
                        m = fminf(m, s0[MS+1]  - sk[koff + 0]);
                        v = m;
                    } else {
                        float m = s0[-MS-1] + sk[koff + 0];
                        m = fmaxf(m, s0[-MS  ] + sk[koff + 1]);
                        m = fmaxf(m, s0[-MS+1] + sk[koff + 2]);
                        m = fmaxf(m, s0[-1]    + sk[koff + 3]);
                        m = fmaxf(m, s0[0]     + sk[koff + 4]);
                        m = fmaxf(m, s0[1]     + sk[koff + 5]);
                        m = fmaxf(m, s0[MS-1]  + sk[koff + 6]);
                        m = fmaxf(m, s0[MS  ]  + sk[koff + 7]);
                        m = fmaxf(m, s0[MS+1]  + sk[koff + 8]);
                        v = m;
                    }
                } else {
                    v = sm[cur][i];
                }
                sm[1-cur][i] = v;
            }
        }
        __syncthreads();
        cur ^= 1;
    }
    int tx = t & 63, tyq = t >> 6;
#pragma unroll
    for (int k = 0; k < 16; k++) {
        int r = tyq + 4*k;
        xc[boff + (size_t)(oy + MHL + r)*W0 + (ox + MHL + tx)] =
            sm[cur][(r + MHL)*MS + (tx + MHL)];
    }
}

// ---------------- conv1 (1->8) + relu + bn1, channel-first, packed FMA ----------------
__global__ void conv1_k(const float* __restrict__ xc, const float* __restrict__ w,
                        const float* __restrict__ bias,
                        const float* __restrict__ gg, const float* __restrict__ bb,
                        const float* __restrict__ mm, const float* __restrict__ vv,
                        float* __restrict__ out) {
    __shared__ float ws[72];
    int t = threadIdx.x;
    if (t < 72) ws[t] = w[t];
    __syncthreads();
    int y = blockIdx.x, b = blockIdx.y;
    int x = t;
    if (x >= 254) return;
    const float* base = xc + ((size_t)b*H0 + y)*W0 + x;
    u64t acc[4];
#pragma unroll
    for (int p = 0; p < 4; p++) acc[p] = pk2(bias[2*p], bias[2*p+1]);
#pragma unroll
    for (int tap = 0; tap < 9; tap++) {
        float v = base[(tap/3)*W0 + (tap%3)];
        u64t pv = pk2(v, v);
        const u64t* wq = (const u64t*)(ws + tap*8);
#pragma unroll
        for (int p = 0; p < 4; p++) fma2(acc[p], pv, wq[p]);
    }
#pragma unroll
    for (int p = 0; p < 4; p++) {
        float a0, a1; upk2(acc[p], a0, a1);
        int k0 = 2*p, k1 = 2*p+1;
        float s0 = gg[k0] * rsqrtf(vv[k0] + BN_EPS);
        float s1 = gg[k1] * rsqrtf(vv[k1] + BN_EPS);
        out[((size_t)(b*8 + k0)*254 + y)*254 + x] = s0*(fmaxf(a0,0.f) - mm[k0]) + bb[k0];
        out[((size_t)(b*8 + k1)*254 + y)*254 + x] = s1*(fmaxf(a1,0.f) - mm[k1]) + bb[k1];
    }
}

// ---------------- register-tiled 3x3 conv, f32x2 FMA, 8 spatial x 8 co per thread ----------------
// MODE 1: store bn(relu(conv+b))              (conv3)
// MODE 2: global max of relu(conv+b)          (conv4; pool dropped: max o pool == max)
// MODE 3: store bn(maxpool2(relu(conv+b)))    (conv2, fused pool)
template<int CI, int CO, int HIN, int WIN, int TW, int ROWS, int MODE>
__global__ __launch_bounds__(256)
void conv_k(const float* __restrict__ gin, const float* __restrict__ gw,
            const float* __restrict__ gb,
            const float* __restrict__ bng, const float* __restrict__ bnb,
            const float* __restrict__ bnm, const float* __restrict__ bnv,
            float* __restrict__ gout) {
    constexpr int WOUT = WIN - 2, HOUT = HIN - 2;
    constexpr int NCOG = CO / 8;
    constexpr int SPR  = TW / 8;
    static_assert(NCOG*SPR*ROWS == 256, "thread mapping");
    constexpr int CC   = 8;
    constexpr int NCH  = CI / CC;
    constexpr int STR  = TW + 8;        // 72, keeps 16B alignment per row
    constexpr int LW   = TW + 2;
    constexpr int IROWS = ROWS + 2;

    __shared__ __align__(16) float in_s[CC*IROWS*STR];
    __shared__ float w_s[9*CC*CO];
    __shared__ float smax[(MODE == 2) ? CO : 1];

    int tid = threadIdx.x;
    int cog  = tid % NCOG;
    int slot = tid / NCOG;
    int yl = slot / SPR;
    int xo = (slot % SPR) * 8;
    int ox0 = blockIdx.x * TW, oy0 = blockIdx.y * ROWS;
    int b = blockIdx.z;

    u64t acc[8][4];
#pragma unroll
    for (int m = 0; m < 8; m++)
#pragma unroll
        for (int p = 0; p < 4; p++) acc[m][p] = 0ull;
    if (MODE == 2 && tid < CO) smax[tid] = 0.f;

    for (int cc = 0; cc < NCH; cc++) {
        __syncthreads();
        for (int idx = tid; idx < CC*IROWS*LW; idx += 256) {
            int ci = idx / (IROWS*LW), rem = idx % (IROWS*LW);
            int yy = rem / LW, xx = rem % LW;
            int gy = oy0 + yy, gx = ox0 + xx;
            float v = 0.f;
            if (gy < HIN && gx < WIN)
                v = gin[((size_t)(b*CI + cc*CC + ci)*HIN + gy)*WIN + gx];
            in_s[ci*(IROWS*STR) + yy*STR + xx] = v;
        }
        for (int idx = tid; idx < 9*CC*CO; idx += 256) {
            int tap = idx / (CC*CO), r = idx - tap*(CC*CO);
            w_s[idx] = gw[tap*(CI*CO) + cc*(CC*CO) + r];
        }
        __syncthreads();
#pragma unroll 2
        for (int ci = 0; ci < CC; ci++) {
#pragma unroll
            for (int dy = 0; dy < 3; dy++) {
                const float* ip = in_s + ci*(IROWS*STR) + (yl+dy)*STR + xo;
                float4 ra = *(const float4*)(ip);
                float4 rb = *(const float4*)(ip+4);
                float4 rc = *(const float4*)(ip+8);
                u64t pv[10];
                pv[0] = pk2(ra.x, ra.x); pv[1] = pk2(ra.y, ra.y);
                pv[2] = pk2(ra.z, ra.z); pv[3] = pk2(ra.w, ra.w);
                pv[4] = pk2(rb.x, rb.x); pv[5] = pk2(rb.y, rb.y);
                pv[6] = pk2(rb.z, rb.z); pv[7] = pk2(rb.w, rb.w);
                pv[8] = pk2(rc.x, rc.x); pv[9] = pk2(rc.y, rc.y);
#pragma unroll
                for (int dx = 0; dx < 3; dx++) {
                    const u64t* wq = (const u64t*)(w_s + (dy*3+dx)*(CC*CO) + ci*CO + cog*8);
                    u64t w0 = wq[0], w1 = wq[1], w2 = wq[2], w3 = wq[3];
#pragma unroll
                    for (int m = 0; m < 8; m++) {
                        fma2(acc[m][0], pv[dx+m], w0);
                        fma2(acc[m][1], pv[dx+m], w1);
                        fma2(acc[m][2], pv[dx+m], w2);
                        fma2(acc[m][3], pv[dx+m], w3);
                    }
                }
            }
        }
    }

    // unpack + bias + relu
    float r[8][8];
    float bia[8];
#pragma unroll
    for (int k = 0; k < 8; k++) bia[k] = gb[cog*8 + k];
#pragma unroll
    for (int m = 0; m < 8; m++)
#pragma unroll
        for (int p = 0; p < 4; p++) {
            float a0, a1; upk2(acc[m][p], a0, a1);
            r[m][2*p]   = fmaxf(a0 + bia[2*p],   0.f);
            r[m][2*p+1] = fmaxf(a1 + bia[2*p+1], 0.f);
        }

    int oy = oy0 + yl;

    if (MODE == 2) {
        float lm[8];
#pragma unroll
        for (int k = 0; k < 8; k++) lm[k] = 0.f;
        if (oy < HOUT) {
#pragma unroll
            for (int m = 0; m < 8; m++)
                if (ox0 + xo + m < WOUT)
#pragma unroll
                    for (int k = 0; k < 8; k++) lm[k] = fmaxf(lm[k], r[m][k]);
        }
#pragma unroll
        for (int k = 0; k < 8; k++)
            atomicMax((int*)&smax[cog*8 + k], __float_as_int(lm[k]));
        __syncthreads();
        if (tid < CO)
            atomicMax((int*)&gout[b*CO + tid], __float_as_int(smax[tid]));
    } else if (MODE == 3) {
        // x-pool pairs (m,m+1) -> 4 pooled cols per thread
        float xp[4][8];
#pragma unroll
        for (int q = 0; q < 4; q++)
#pragma unroll
            for (int k = 0; k < 8; k++)
                xp[q][k] = fmaxf(r[2*q][k], r[2*q+1][k]);
        int py = yl >> 1;
        int pxb = xo >> 1;   // pooled col base (0..28, step 4)
        float* pool_s = in_s;  // alias (>= 8*32*CO floats available)
        __syncthreads();       // done with in_s contents
        if (yl & 1) {
#pragma unroll
            for (int q = 0; q < 4; q++)
#pragma unroll
                for (int k = 0; k < 8; k++)
                    pool_s[((py*(TW/2) + pxb + q)*CO) + cog*8 + k] = xp[q][k];
        }
        __syncthreads();
        if (!(yl & 1)) {
            int gy_p = oy >> 1;
            if (gy_p < HOUT/2) {
#pragma unroll
                for (int q = 0; q < 4; q++) {
                    int gx_p = ((ox0 + xo) >> 1) + q;
                    if (gx_p < WOUT/2) {
#pragma unroll
                        for (int k = 0; k < 8; k++) {
                            int co = cog*8 + k;
                            float v = fmaxf(xp[q][k],
                                pool_s[((py*(TW/2) + pxb + q)*CO) + co]);
                            float sc = bng[co] * rsqrtf(bnv[co] + BN_EPS);
                            v = sc*(v - bnm[co]) + bnb[co];
                            gout[((size_t)(b*CO + co)*(HOUT/2) + gy_p)*(WOUT/2) + gx_p] = v;
                        }
                    }
                }
            }
        }
    } else {  // MODE 1
        if (oy < HOUT) {
            float sc[8], sb[8], sm_[8];
#pragma unroll
            for (int k = 0; k < 8; k++) {
                int co = cog*8 + k;
                sc[k] = bng[co] * rsqrtf(bnv[co] + BN_EPS);
                sb[k] = bnb[co];
                sm_[k] = bnm[co];
            }
#pragma unroll
            for (int m = 0; m < 8; m++) {
                int ox = ox0 + xo + m;
                if (ox < WOUT) {
#pragma unroll
                    for (int k = 0; k < 8; k++) {
                        float v = sc[k]*(r[m][k] - sm_[k]) + sb[k];
                        gout[((size_t)(b*CO + cog*8 + k)*HOUT + oy)*WOUT + ox] = v;
                    }
                }
            }
        }
    }
}

// ---------------- dense ----------------
__global__ void dense_k(const float* __restrict__ gm, const float* __restrict__ dw,
                        const float* __restrict__ db, float* __restrict__ h,
                        float* __restrict__ out_tail) {
    int b = threadIdx.x;
    if (b >= B) return;
    float s = db[0];
#pragma unroll
    for (int c = 0; c < 32; c++) s = fmaf(gm[b*32 + c], dw[c], s);
    h[b] = s;
    out_tail[b] = s;
}

// ---------------- geodesic reconstruction: 5 fused steps, 64x64 tile ----------------
#define RK 5
#define RT 64
#define RS (RT + 2*RK)
#define RCELL (RS*RS)
#define RNIT ((RCELL + 255)/256)
template<bool INIT>
__global__ __launch_bounds__(256)
void recon_k(const float* __restrict__ src, const float* __restrict__ mask,
             const float* __restrict__ h, float* __restrict__ dst) {
    __shared__ float sm[2][RCELL];
    int t = threadIdx.x;
    int ox = blockIdx.x*RT - RK;
    int oy = blockIdx.y*RT - RK;
    const size_t boff = (size_t)blockIdx.z*H0*W0;
    const float hv = INIT ? h[blockIdx.z] : 0.f;

    float mk[RNIT];
    bool  inter[RNIT];
#pragma unroll
    for (int k = 0; k < RNIT; k++) {
        int i = t + k*256;
        float sv = -CUDART_INF_F, mv = -CUDART_INF_F;
        bool it = false;
        if (i < RCELL) {
            int ly = i / RS, lx = i % RS;
            int gy = oy + ly, gx = ox + lx;
            if (gy >= 0 && gy < H0 && gx >= 0 && gx < W0) {
                mv = mask[boff + gy*W0 + gx];
                sv = INIT ? (mv - hv) : src[boff + gy*W0 + gx];
            }
            sm[0][i] = sv;
            it = (ly > 0 && ly < RS-1 && lx > 0 && lx < RS-1);
        }
        mk[k] = mv;
        inter[k] = it;
    }
    __syncthreads();
    int cur = 0;
#pragma unroll
    for (int step = 0; step < RK; step++) {
#pragma unroll
        for (int k = 0; k < RNIT; k++) {
            int i = t + k*256;
            if (i < RCELL) {
                float v;
                if (inter[k]) {
                    const float* s0 = &sm[cur][i];
                    float a = fmaxf(fmaxf(s0[-RS-1], s0[-RS]), s0[-RS+1]);
                    float c = fmaxf(fmaxf(s0[-1],    s0[0]),   s0[1]);
                    float d = fmaxf(fmaxf(s0[RS-1],  s0[RS]),  s0[RS+1]);
                    v = fminf(fmaxf(fmaxf(a, c), d), mk[k]);
                } else {
                    v = sm[cur][i];
                }
                sm[1-cur][i] = v;
            }
        }
        __syncthreads();
        cur ^= 1;
    }
    int tx = t & 63, tyq = t >> 6;
#pragma unroll
    for (int k = 0; k < 16; k++) {
        int r = tyq + 4*k;
        dst[boff + (size_t)(oy + RK + r)*W0 + (ox + RK + tx)] =
            sm[cur][(r + RK)*RS + (tx + RK)];
    }
}

// ---------------- launch ----------------
extern "C" void kernel_launch(void* const* d_in, const int* in_sizes, int n_in,
                              void* d_out, int out_size) {
    const float* x    = (const float*)d_in[0];
    const float* ko   = (const float*)d_in[1];
    const float* kc   = (const float*)d_in[2];
    const float* w1   = (const float*)d_in[3];
    const float* b1   = (const float*)d_in[4];
    const float* w2   = (const float*)d_in[5];
    const float* b2   = (const float*)d_in[6];
    const float* w3   = (const float*)d_in[7];
    const float* b3   = (const float*)d_in[8];
    const float* w4   = (const float*)d_in[9];
    const float* b4   = (const float*)d_in[10];
    const float* bn1g = (const float*)d_in[11];
    const float* bn1b = (const float*)d_in[12];
    const float* bn1m = (const float*)d_in[13];
    const float* bn1v = (const float*)d_in[14];
    const float* bn2g = (const float*)d_in[15];
    const float* bn2b = (const float*)d_in[16];
    const float* bn2m = (const float*)d_in[17];
    const float* bn2v = (const float*)d_in[18];
    const float* bn3g = (const float*)d_in[19];
    const float* bn3b = (const float*)d_in[20];
    const float* bn3m = (const float*)d_in[21];
    const float* bn3v = (const float*)d_in[22];
    const float* dw   = (const float*)d_in[23];
    const float* db   = (const float*)d_in[24];
    float* out = (float*)d_out;

    float *MA, *MB, *XC, *Y1, *Y2, *Y3, *GM, *HH;
    cudaGetSymbolAddress((void**)&MA, g_MA);
    cudaGetSymbolAddress((void**)&MB, g_MB);
    cudaGetSymbolAddress((void**)&XC, g_XC);
    cudaGetSymbolAddress((void**)&Y1, g_Y1);
    cudaGetSymbolAddress((void**)&Y2, g_Y2);
    cudaGetSymbolAddress((void**)&Y3, g_Y3);
    cudaGetSymbolAddress((void**)&GM, g_GM);
    cudaGetSymbolAddress((void**)&HH, g_H);

    // fused morphology -> XC
    morph4_k<<<dim3(4, 4, B), 256>>>(x, XC, ko, kc);

    // CNN (channel-first intermediates)
    conv1_k<<<dim3(254, B), 256>>>(XC, w1, b1, bn1g, bn1b, bn1m, bn1v, Y1);
    conv_k<8, 16, 254, 254, 64, 16, 3><<<dim3(4, 16, B), 256>>>(
        Y1, w2, b2, bn2g, bn2b, bn2m, bn2v, Y2);
    conv_k<16, 32, 126, 126, 64, 8, 1><<<dim3(2, 16, B), 256>>>(
        Y2, w3, b3, bn3g, bn3b, bn3m, bn3v, Y3);
    cudaMemsetAsync(GM, 0, B*32*sizeof(float));
    conv_k<32, 32, 124, 124, 64, 8, 2><<<dim3(2, 16, B), 256>>>(
        Y3, w4, b4, nullptr, nullptr, nullptr, nullptr, GM);
    dense_k<<<1, 32>>>(GM, dw, db, HH, out + (size_t)NPIX);

    // h-maxima: 50 steps = 10 launches of 5 fused steps (first fuses marker init)
    recon_k<true><<<dim3(4, 4, B), 256>>>(XC, XC, HH, MB);
    for (int l = 1; l < 10; l++) {
        float* srcp = (l & 1) ? MB : MA;
        float* dstp = (l == 9) ? out : ((l & 1) ? MA : MB);
        recon_k<false><<<dim3(4, 4, B), 256>>>(srcp, XC, nullptr, dstp);
    }
}

// round 5
// speedup vs baseline: 3.5505x; 1.0078x over previous
#include <cuda_runtime.h>
#include <math_constants.h>

#define B 32
#define H0 256
#define W0 256
#define NPIX (B*H0*W0)
#define BN_EPS 1e-3f

typedef unsigned long long u64t;

__device__ __forceinline__ u64t pk2(float a, float b) {
    u64t r; asm("mov.b64 %0,{%1,%2};" : "=l"(r) : "f"(a), "f"(b)); return r;
}
__device__ __forceinline__ void upk2(u64t v, float& a, float& b) {
    asm("mov.b64 {%0,%1},%2;" : "=f"(a), "=f"(b) : "l"(v));
}
__device__ __forceinline__ void fma2(u64t& d, u64t a, u64t b) {
    asm("fma.rn.f32x2 %0,%1,%2,%0;" : "+l"(d) : "l"(a), "l"(b));
}

// ---------------- scratch ----------------
__device__ float g_MA[NPIX];
__device__ float g_MB[NPIX];
__device__ float g_XC[NPIX];
__device__ float g_Y1[(size_t)B*8*254*254];
__device__ float g_Y2[(size_t)B*16*126*126];
__device__ float g_Y3[(size_t)B*32*124*124];
__device__ float g_GM[B*32];
__device__ float g_H[B];

// ---------------- fused 4-pass morphology: E(ko),D(ko),D(kc),E(kc), halo 4 ----------------
#define MT 64
#define MHL 4
#define MS (MT + 2*MHL)
#define MCELL (MS*MS)
#define MNIT ((MCELL + 255)/256)
__global__ __launch_bounds__(256)
void morph4_k(const float* __restrict__ x, float* __restrict__ xc,
              const float* __restrict__ ko, const float* __restrict__ kc) {
    __shared__ float sm[2][MCELL];
    __shared__ float sk[18];
    int t = threadIdx.x;
    if (t < 18) sk[t] = (t < 9) ? ko[t] : kc[t - 9];
    int ox = blockIdx.x*MT - MHL;
    int oy = blockIdx.y*MT - MHL;
    const size_t boff = (size_t)blockIdx.z*H0*W0;

    bool inb[MNIT], inter[MNIT];
#pragma unroll
    for (int k = 0; k < MNIT; k++) {
        int i = t + k*256;
        bool ib = false, it = false;
        if (i < MCELL) {
            int ly = i / MS, lx = i % MS;
            int gy = oy + ly, gx = ox + lx;
            ib = (gy >= 0 && gy < H0 && gx >= 0 && gx < W0);
            sm[0][i] = ib ? x[boff + gy*W0 + gx] : CUDART_INF_F;
            it = (ly > 0 && ly < MS-1 && lx > 0 && lx < MS-1);
        }
        inb[k] = ib; inter[k] = it;
    }
    __syncthreads();
    int cur = 0;
#pragma unroll
    for (int op = 0; op < 4; op++) {
        const bool ero = (op == 0 || op == 3);
        const int koff = (op < 2) ? 0 : 9;
        const float nextpad = (op >= 2) ? CUDART_INF_F : -CUDART_INF_F;
#pragma unroll
        for (int k = 0; k < MNIT; k++) {
            int i = t + k*256;
            if (i < MCELL) {
                float v;
                if (!inb[k]) {
                    v = nextpad;
                } else if (inter[k]) {
                    const float* s0 = &sm[cur][i];
                    if (ero) {
                        float m = s0[-MS-1] - sk[koff + 8];
                        m = fminf(m, s0[-MS  ] - sk[koff + 7]);
                        m = fminf(m, s0[-MS+1] - sk[koff + 6]);
                        m = fminf(m, s0[-1]    - sk[koff + 5]);
                        m = fminf(m, s0[0]     - sk[koff + 4]);
                        m = fminf(m, s0[1]     - sk[koff + 3]);
                        m = fminf(m, s0[MS-1]  - sk[koff + 2]);
                        m = fminf(m, s0[MS  ]  - sk[koff + 1]);
                        m = fminf(m, s0[MS+1]  - sk[koff + 0]);
                        v = m;
                    } else {
                        float m = s0[-MS-1] + sk[koff + 0];
                        m = fmaxf(m, s0[-MS  ] + sk[koff + 1]);
                        m = fmaxf(m, s0[-MS+1] + sk[koff + 2]);
                        m = fmaxf(m, s0[-1]    + sk[koff + 3]);
                        m = fmaxf(m, s0[0]     + sk[koff + 4]);
                        m = fmaxf(m, s0[1]     + sk[koff + 5]);
                        m = fmaxf(m, s0[MS-1]  + sk[koff + 6]);
                        m = fmaxf(m, s0[MS  ]  + sk[koff + 7]);
                        m = fmaxf(m, s0[MS+1]  + sk[koff + 8]);
                        v = m;
                    }
                } else {
                    v = sm[cur][i];
                }
                sm[1-cur][i] = v;
            }
        }
        __syncthreads();
        cur ^= 1;
    }
    int tx = t & 63, tyq = t >> 6;
#pragma unroll
    for (int k = 0; k < 16; k++) {
        int r = tyq + 4*k;
        xc[boff + (size_t)(oy + MHL + r)*W0 + (ox + MHL + tx)] =
            sm[cur][(r + MHL)*MS + (tx + MHL)];
    }
}

// ---------------- conv1 (1->8) + relu + bn1, channel-first, packed FMA ----------------
__global__ void conv1_k(const float* __restrict__ xc, const float* __restrict__ w,
                        const float* __restrict__ bias,
                        const float* __restrict__ gg, const float* __restrict__ bb,
                        const float* __restrict__ mm, const float* __restrict__ vv,
                        float* __restrict__ out) {
    __shared__ float ws[72];
    int t = threadIdx.x;
    if (t < 72) ws[t] = w[t];
    __syncthreads();
    int y = blockIdx.x, b = blockIdx.y;
    int x = t;
    if (x >= 254) return;
    const float* base = xc + ((size_t)b*H0 + y)*W0 + x;
    u64t acc[4];
#pragma unroll
    for (int p = 0; p < 4; p++) acc[p] = pk2(bias[2*p], bias[2*p+1]);
#pragma unroll
    for (int tap = 0; tap < 9; tap++) {
        float v = base[(tap/3)*W0 + (tap%3)];
        u64t pv = pk2(v, v);
        const u64t* wq = (const u64t*)(ws + tap*8);
#pragma unroll
        for (int p = 0; p < 4; p++) fma2(acc[p], pv, wq[p]);
    }
#pragma unroll
    for (int p = 0; p < 4; p++) {
        float a0, a1; upk2(acc[p], a0, a1);
        int k0 = 2*p, k1 = 2*p+1;
        float s0 = gg[k0] * rsqrtf(vv[k0] + BN_EPS);
        float s1 = gg[k1] * rsqrtf(vv[k1] + BN_EPS);
        out[((size_t)(b*8 + k0)*254 + y)*254 + x] = s0*(fmaxf(a0,0.f) - mm[k0]) + bb[k0];
        out[((size_t)(b*8 + k1)*254 + y)*254 + x] = s1*(fmaxf(a1,0.f) - mm[k1]) + bb[k1];
    }
}

// ---------------- register-tiled 3x3 conv, f32x2 FMA, 4 spatial x 8 co per thread ----------------
// Full weight preload; input in 8-ci chunks. TW=32.
// MODE 1: store bn(relu(conv+b))              (conv3)
// MODE 2: global max of relu(conv+b)          (conv4; pool dropped: max o pool == max)
// MODE 3: store bn(maxpool2(relu(conv+b)))    (conv2, fused pool)
template<int CI, int CO, int HIN, int WIN, int MODE>
__global__ __launch_bounds__(256, 3)
void conv_k(const float* __restrict__ gin, const float* __restrict__ gw,
            const float* __restrict__ gb,
            const float* __restrict__ bng, const float* __restrict__ bnb,
            const float* __restrict__ bnm, const float* __restrict__ bnv,
            float* __restrict__ gout) {
    constexpr int WOUT = WIN - 2, HOUT = HIN - 2;
    constexpr int TW   = 32;
    constexpr int NCOG = CO / 8;
    constexpr int SPR  = TW / 4;            // 8
    constexpr int ROWS = 256 / (NCOG*SPR);  // 16 (CO=16) or 8 (CO=32)
    constexpr int CC   = 8;
    constexpr int NCH  = CI / CC;
    constexpr int STR  = TW + 4;            // 36 (16B-aligned rows)
    constexpr int LW   = TW + 2;
    constexpr int IROWS = ROWS + 2;

    __shared__ __align__(16) float in_s[CC*IROWS*STR];
    __shared__ __align__(16) float w_s[9*CI*CO];
    __shared__ float smax[(MODE == 2) ? CO : 1];

    int tid = threadIdx.x;
    int cog  = tid % NCOG;
    int slot = tid / NCOG;
    int yl = slot / SPR;
    int xo = (slot % SPR) * 4;
    int ox0 = blockIdx.x * TW, oy0 = blockIdx.y * ROWS;
    int b = blockIdx.z;

    // full weight preload (layout identical to global HWIO)
    for (int idx = tid; idx < 9*CI*CO; idx += 256) w_s[idx] = gw[idx];
    if (MODE == 2 && tid < CO) smax[tid] = 0.f;

    u64t acc[4][4];
#pragma unroll
    for (int m = 0; m < 4; m++)
#pragma unroll
        for (int p = 0; p < 4; p++) acc[m][p] = 0ull;

    for (int cc = 0; cc < NCH; cc++) {
        __syncthreads();
        for (int idx = tid; idx < CC*IROWS*LW; idx += 256) {
            int ci = idx / (IROWS*LW), rem = idx % (IROWS*LW);
            int yy = rem / LW, xx = rem % LW;
            int gy = oy0 + yy, gx = ox0 + xx;
            float v = 0.f;
            if (gy < HIN && gx < WIN)
                v = gin[((size_t)(b*CI + cc*CC + ci)*HIN + gy)*WIN + gx];
            in_s[ci*(IROWS*STR) + yy*STR + xx] = v;
        }
        __syncthreads();
#pragma unroll 2
        for (int ci = 0; ci < CC; ci++) {
            const int cig = cc*CC + ci;
#pragma unroll
            for (int dy = 0; dy < 3; dy++) {
                const float* ip = in_s + ci*(IROWS*STR) + (yl+dy)*STR + xo;
                float4 ra = *(const float4*)(ip);
                float2 rb = *(const float2*)(ip+4);
                u64t pv[6];
                pv[0] = pk2(ra.x, ra.x); pv[1] = pk2(ra.y, ra.y);
                pv[2] = pk2(ra.z, ra.z); pv[3] = pk2(ra.w, ra.w);
                pv[4] = pk2(rb.x, rb.x); pv[5] = pk2(rb.y, rb.y);
#pragma unroll
                for (int dx = 0; dx < 3; dx++) {
                    const u64t* wq = (const u64t*)(w_s + (dy*3+dx)*(CI*CO) + cig*CO + cog*8);
                    u64t w0 = wq[0], w1 = wq[1], w2 = wq[2], w3 = wq[3];
#pragma unroll
                    for (int m = 0; m < 4; m++) {
                        fma2(acc[m][0], pv[dx+m], w0);
                        fma2(acc[m][1], pv[dx+m], w1);
                        fma2(acc[m][2], pv[dx+m], w2);
                        fma2(acc[m][3], pv[dx+m], w3);
                    }
                }
            }
        }
    }

    // unpack + bias + relu
    float r[4][8];
    float bia[8];
#pragma unroll
    for (int k = 0; k < 8; k++) bia[k] = gb[cog*8 + k];
#pragma unroll
    for (int m = 0; m < 4; m++)
#pragma unroll
        for (int p = 0; p < 4; p++) {
            float a0, a1; upk2(acc[m][p], a0, a1);
            r[m][2*p]   = fmaxf(a0 + bia[2*p],   0.f);
            r[m][2*p+1] = fmaxf(a1 + bia[2*p+1], 0.f);
        }

    int oy = oy0 + yl;

    if (MODE == 2) {
        float lm[8];
#pragma unroll
        for (int k = 0; k < 8; k++) lm[k] = 0.f;
        if (oy < HOUT) {
#pragma unroll
            for (int m = 0; m < 4; m++)
                if (ox0 + xo + m < WOUT)
#pragma unroll
                    for (int k = 0; k < 8; k++) lm[k] = fmaxf(lm[k], r[m][k]);
        }
#pragma unroll
        for (int k = 0; k < 8; k++)
            atomicMax((int*)&smax[cog*8 + k], __float_as_int(lm[k]));
        __syncthreads();
        if (tid < CO)
            atomicMax((int*)&gout[b*CO + tid], __float_as_int(smax[tid]));
    } else if (MODE == 3) {
        // x-pool pairs -> 2 pooled cols per thread; y via smem exchange (alias in_s)
        float xp[2][8];
#pragma unroll
        for (int q = 0; q < 2; q++)
#pragma unroll
            for (int k = 0; k < 8; k++)
                xp[q][k] = fmaxf(r[2*q][k], r[2*q+1][k]);
        int py = yl >> 1;
        int pxb = xo >> 1;
        float* pool_s = in_s;
        __syncthreads();
        if (yl & 1) {
#pragma unroll
            for (int q = 0; q < 2; q++)
#pragma unroll
                for (int k = 0; k < 8; k++)
                    pool_s[((py*(TW/2) + pxb + q)*CO) + cog*8 + k] = xp[q][k];
        }
        __syncthreads();
        if (!(yl & 1)) {
            int gy_p = oy >> 1;
            if (gy_p < HOUT/2) {
#pragma unroll
                for (int q = 0; q < 2; q++) {
                    int gx_p = ((ox0 + xo) >> 1) + q;
                    if (gx_p < WOUT/2) {
#pragma unroll
                        for (int k = 0; k < 8; k++) {
                            int co = cog*8 + k;
                            float v = fmaxf(xp[q][k],
                                pool_s[((py*(TW/2) + pxb + q)*CO) + co]);
                            float sc = bng[co] * rsqrtf(bnv[co] + BN_EPS);
                            v = sc*(v - bnm[co]) + bnb[co];
                            gout[((size_t)(b*CO + co)*(HOUT/2) + gy_p)*(WOUT/2) + gx_p] = v;
                        }
                    }
                }
            }
        }
    } else {  // MODE 1
        if (oy < HOUT) {
            float sc[8], sb[8], sm_[8];
#pragma unroll
            for (int k = 0; k < 8; k++) {
                int co = cog*8 + k;
                sc[k] = bng[co] * rsqrtf(bnv[co] + BN_EPS);
                sb[k] = bnb[co];
                sm_[k] = bnm[co];
            }
#pragma unroll
            for (int m = 0; m < 4; m++) {
                int ox = ox0 + xo + m;
                if (ox < WOUT) {
#pragma unroll
                    for (int k = 0; k < 8; k++) {
                        float v = sc[k]*(r[m][k] - sm_[k]) + sb[k];
                        gout[((size_t)(b*CO + cog*8 + k)*HOUT + oy)*WOUT + ox] = v;
                    }
                }
            }
        }
    }
}

// ---------------- dense ----------------
__global__ void dense_k(const float* __restrict__ gm, const float* __restrict__ dw,
                        const float* __restrict__ db, float* __restrict__ h,
                        float* __restrict__ out_tail) {
    int b = threadIdx.x;
    if (b >= B) return;
    float s = db[0];
#pragma unroll
    for (int c = 0; c < 32; c++) s = fmaf(gm[b*32 + c], dw[c], s);
    h[b] = s;
    out_tail[b] = s;
}

// ---------------- geodesic reconstruction: 5 fused steps, 64x64 tile ----------------
#define RK 5
#define RT 64
#define RS (RT + 2*RK)
#define RCELL (RS*RS)
#define RNIT ((RCELL + 255)/256)
template<bool INIT>
__global__ __launch_bounds__(256)
void recon_k(const float* __restrict__ src, const float* __restrict__ mask,
             const float* __restrict__ h, float* __restrict__ dst) {
    __shared__ float sm[2][RCELL];
    int t = threadIdx.x;
    int ox = blockIdx.x*RT - RK;
    int oy = blockIdx.y*RT - RK;
    const size_t boff = (size_t)blockIdx.z*H0*W0;
    const float hv = INIT ? h[blockIdx.z] : 0.f;

    float mk[RNIT];
    bool  inter[RNIT];
#pragma unroll
    for (int k = 0; k < RNIT; k++) {
        int i = t + k*256;
        float sv = -CUDART_INF_F, mv = -CUDART_INF_F;
        bool it = false;
        if (i < RCELL) {
            int ly = i / RS, lx = i % RS;
            int gy = oy + ly, gx = ox + lx;
            if (gy >= 0 && gy < H0 && gx >= 0 && gx < W0) {
                mv = mask[boff + gy*W0 + gx];
                sv = INIT ? (mv - hv) : src[boff + gy*W0 + gx];
            }
            sm[0][i] = sv;
            it = (ly > 0 && ly < RS-1 && lx > 0 && lx < RS-1);
        }
        mk[k] = mv;
        inter[k] = it;
    }
    __syncthreads();
    int cur = 0;
#pragma unroll
    for (int step = 0; step < RK; step++) {
#pragma unroll
        for (int k = 0; k < RNIT; k++) {
            int i = t + k*256;
            if (i < RCELL) {
                float v;
                if (inter[k]) {
                    const float* s0 = &sm[cur][i];
                    float a = fmaxf(fmaxf(s0[-RS-1], s0[-RS]), s0[-RS+1]);
                    float c = fmaxf(fmaxf(s0[-1],    s0[0]),   s0[1]);
                    float d = fmaxf(fmaxf(s0[RS-1],  s0[RS]),  s0[RS+1]);
                    v = fminf(fmaxf(fmaxf(a, c), d), mk[k]);
                } else {
                    v = sm[cur][i];
                }
                sm[1-cur][i] = v;
            }
        }
        __syncthreads();
        cur ^= 1;
    }
    int tx = t & 63, tyq = t >> 6;
#pragma unroll
    for (int k = 0; k < 16; k++) {
        int r = tyq + 4*k;
        dst[boff + (size_t)(oy + RK + r)*W0 + (ox + RK + tx)] =
            sm[cur][(r + RK)*RS + (tx + RK)];
    }
}

// ---------------- launch ----------------
extern "C" void kernel_launch(void* const* d_in, const int* in_sizes, int n_in,
                              void* d_out, int out_size) {
    const float* x    = (const float*)d_in[0];
    const float* ko   = (const float*)d_in[1];
    const float* kc   = (const float*)d_in[2];
    const float* w1   = (const float*)d_in[3];
    const float* b1   = (const float*)d_in[4];
    const float* w2   = (const float*)d_in[5];
    const float* b2   = (const float*)d_in[6];
    const float* w3   = (const float*)d_in[7];
    const float* b3   = (const float*)d_in[8];
    const float* w4   = (const float*)d_in[9];
    const float* b4   = (const float*)d_in[10];
    const float* bn1g = (const float*)d_in[11];
    const float* bn1b = (const float*)d_in[12];
    const float* bn1m = (const float*)d_in[13];
    const float* bn1v = (const float*)d_in[14];
    const float* bn2g = (const float*)d_in[15];
    const float* bn2b = (const float*)d_in[16];
    const float* bn2m = (const float*)d_in[17];
    const float* bn2v = (const float*)d_in[18];
    const float* bn3g = (const float*)d_in[19];
    const float* bn3b = (const float*)d_in[20];
    const float* bn3m = (const float*)d_in[21];
    const float* bn3v = (const float*)d_in[22];
    const float* dw   = (const float*)d_in[23];
    const float* db   = (const float*)d_in[24];
    float* out = (float*)d_out;

    float *MA, *MB, *XC, *Y1, *Y2, *Y3, *GM, *HH;
    cudaGetSymbolAddress((void**)&MA, g_MA);
    cudaGetSymbolAddress((void**)&MB, g_MB);
    cudaGetSymbolAddress((void**)&XC, g_XC);
    cudaGetSymbolAddress((void**)&Y1, g_Y1);
    cudaGetSymbolAddress((void**)&Y2, g_Y2);
    cudaGetSymbolAddress((void**)&Y3, g_Y3);
    cudaGetSymbolAddress((void**)&GM, g_GM);
    cudaGetSymbolAddress((void**)&HH, g_H);

    // fused morphology -> XC
    morph4_k<<<dim3(4, 4, B), 256>>>(x, XC, ko, kc);

    // CNN (channel-first intermediates)
    conv1_k<<<dim3(254, B), 256>>>(XC, w1, b1, bn1g, bn1b, bn1m, bn1v, Y1);
    conv_k<8, 16, 254, 254, 3><<<dim3(8, 16, B), 256>>>(
        Y1, w2, b2, bn2g, bn2b, bn2m, bn2v, Y2);
    conv_k<16, 32, 126, 126, 1><<<dim3(4, 16, B), 256>>>(
        Y2, w3, b3, bn3g, bn3b, bn3m, bn3v, Y3);
    cudaMemsetAsync(GM, 0, B*32*sizeof(float));
    conv_k<32, 32, 124, 124, 2><<<dim3(4, 16, B), 256>>>(
        Y3, w4, b4, nullptr, nullptr, nullptr, nullptr, GM);
    dense_k<<<1, 32>>>(GM, dw, db, HH, out + (size_t)NPIX);

    // h-maxima: 50 steps = 10 launches of 5 fused steps (first fuses marker init)
    recon_k<true><<<dim3(4, 4, B), 256>>>(XC, XC, HH, MB);
    for (int l = 1; l < 10; l++) {
        float* srcp = (l & 1) ? MB : MA;
        float* dstp = (l == 9) ? out : ((l & 1) ? MA : MB);
        recon_k<false><<<dim3(4, 4, B), 256>>>(srcp, XC, nullptr, dstp);
    }
}

// round 6
// speedup vs baseline: 4.6786x; 1.3177x over previous
#include <cuda_runtime.h>
#include <math_constants.h>

#define B 32
#define H0 256
#define W0 256
#define NPIX (B*H0*W0)
#define BN_EPS 1e-3f

typedef unsigned long long u64t;

__device__ __forceinline__ u64t pk2(float a, float b) {
    u64t r; asm("mov.b64 %0,{%1,%2};" : "=l"(r) : "f"(a), "f"(b)); return r;
}
__device__ __forceinline__ void upk2(u64t v, float& a, float& b) {
    asm("mov.b64 {%0,%1},%2;" : "=f"(a), "=f"(b) : "l"(v));
}
__device__ __forceinline__ void fma2(u64t& d, u64t a, u64t b) {
    asm("fma.rn.f32x2 %0,%1,%2,%0;" : "+l"(d) : "l"(a), "l"(b));
}
__device__ __forceinline__ unsigned tf32r(float v) {
    unsigned r; asm("cvt.rna.tf32.f32 %0,%1;" : "=r"(r) : "f"(v)); return r;
}
#define MMA_TF32(d, a0,a1,a2,a3, b0,b1) \
    asm volatile("mma.sync.aligned.m16n8k8.row.col.f32.tf32.tf32.f32 " \
        "{%0,%1,%2,%3},{%4,%5,%6,%7},{%8,%9},{%0,%1,%2,%3};" \
        : "+f"((d)[0]),"+f"((d)[1]),"+f"((d)[2]),"+f"((d)[3]) \
        : "r"(a0),"r"(a1),"r"(a2),"r"(a3),"r"(b0),"r"(b1))

// ---------------- scratch ----------------
__device__ float g_MA[NPIX];
__device__ float g_MB[NPIX];
__device__ float g_XC[NPIX];
__device__ float g_Y1[(size_t)B*8*254*254];
__device__ float g_Y2[(size_t)B*16*126*126];
__device__ float g_Y3[(size_t)B*32*124*124];
__device__ float g_GM[B*32];
__device__ float g_H[B];

// ---------------- fused 4-pass morphology: E(ko),D(ko),D(kc),E(kc), halo 4 ----------------
#define MT 64
#define MHL 4
#define MS (MT + 2*MHL)
#define MCELL (MS*MS)
#define MNIT ((MCELL + 255)/256)
__global__ __launch_bounds__(256)
void morph4_k(const float* __restrict__ x, float* __restrict__ xc,
              const float* __restrict__ ko, const float* __restrict__ kc) {
    __shared__ float sm[2][MCELL];
    __shared__ float sk[18];
    int t = threadIdx.x;
    if (t < 18) sk[t] = (t < 9) ? ko[t] : kc[t - 9];
    int ox = blockIdx.x*MT - MHL;
    int oy = blockIdx.y*MT - MHL;
    const size_t boff = (size_t)blockIdx.z*H0*W0;

    bool inb[MNIT], inter[MNIT];
#pragma unroll
    for (int k = 0; k < MNIT; k++) {
        int i = t + k*256;
        bool ib = false, it = false;
        if (i < MCELL) {
            int ly = i / MS, lx = i % MS;
            int gy = oy + ly, gx = ox + lx;
            ib = (gy >= 0 && gy < H0 && gx >= 0 && gx < W0);
            sm[0][i] = ib ? x[boff + gy*W0 + gx] : CUDART_INF_F;
            it = (ly > 0 && ly < MS-1 && lx > 0 && lx < MS-1);
        }
        inb[k] = ib; inter[k] = it;
    }
    __syncthreads();
    int cur = 0;
#pragma unroll
    for (int op = 0; op < 4; op++) {
        const bool ero = (op == 0 || op == 3);
        const int koff = (op < 2) ? 0 : 9;
        const float nextpad = (op >= 2) ? CUDART_INF_F : -CUDART_INF_F;
#pragma unroll
        for (int k = 0; k < MNIT; k++) {
            int i = t + k*256;
            if (i < MCELL) {
                float v;
                if (!inb[k]) {
                    v = nextpad;
                } else if (inter[k]) {
                    const float* s0 = &sm[cur][i];
                    if (ero) {
                        float m = s0[-MS-1] - sk[koff + 8];
                        m = fminf(m, s0[-MS  ] - sk[koff + 7]);
                        m = fminf(m, s0[-MS+1] - sk[koff + 6]);
                        m = fminf(m, s0[-1]    - sk[koff + 5]);
                        m = fminf(m, s0[0]     - sk[koff + 4]);
                        m = fminf(m, s0[1]     - sk[koff + 3]);
                        m = fminf(m, s0[MS-1]  - sk[koff + 2]);
                        m = fminf(m, s0[MS  ]  - sk[koff + 1]);
                        m = fminf(m, s0[MS+1]  - sk[koff + 0]);
                        v = m;
                    } else {
                        float m = s0[-MS-1] + sk[koff + 0];
                        m = fmaxf(m, s0[-MS  ] + sk[koff + 1]);
                        m = fmaxf(m, s0[-MS+1] + sk[koff + 2]);
                        m = fmaxf(m, s0[-1]    + sk[koff + 3]);
                        m = fmaxf(m, s0[0]     + sk[koff + 4]);
                        m = fmaxf(m, s0[1]     + sk[koff + 5]);
                        m = fmaxf(m, s0[MS-1]  + sk[koff + 6]);
                        m = fmaxf(m, s0[MS  ]  + sk[koff + 7]);
                        m = fmaxf(m, s0[MS+1]  + sk[koff + 8]);
                        v = m;
                    }
                } else {
                    v = sm[cur][i];
                }
                sm[1-cur][i] = v;
            }
        }
        __syncthreads();
        cur ^= 1;
    }
    int tx = t & 63, tyq = t >> 6;
#pragma unroll
    for (int k = 0; k < 16; k++) {
        int r = tyq + 4*k;
        xc[boff + (size_t)(oy + MHL + r)*W0 + (ox + MHL + tx)] =
            sm[cur][(r + MHL)*MS + (tx + MHL)];
    }
}

// ---------------- conv1 (1->8) + relu + bn1 ----------------
__global__ void conv1_k(const float* __restrict__ xc, const float* __restrict__ w,
                        const float* __restrict__ bias,
                        const float* __restrict__ gg, const float* __restrict__ bb,
                        const float* __restrict__ mm, const float* __restrict__ vv,
                        float* __restrict__ out) {
    __shared__ float ws[72];
    int t = threadIdx.x;
    if (t < 72) ws[t] = w[t];
    __syncthreads();
    int y = blockIdx.x, b = blockIdx.y;
    int x = t;
    if (x >= 254) return;
    const float* base = xc + ((size_t)b*H0 + y)*W0 + x;
    u64t acc[4];
#pragma unroll
    for (int p = 0; p < 4; p++) acc[p] = pk2(bias[2*p], bias[2*p+1]);
#pragma unroll
    for (int tap = 0; tap < 9; tap++) {
        float v = base[(tap/3)*W0 + (tap%3)];
        u64t pv = pk2(v, v);
        const u64t* wq = (const u64t*)(ws + tap*8);
#pragma unroll
        for (int p = 0; p < 4; p++) fma2(acc[p], pv, wq[p]);
    }
#pragma unroll
    for (int p = 0; p < 4; p++) {
        float a0, a1; upk2(acc[p], a0, a1);
        int k0 = 2*p, k1 = 2*p+1;
        float s0 = gg[k0] * rsqrtf(vv[k0] + BN_EPS);
        float s1 = gg[k1] * rsqrtf(vv[k1] + BN_EPS);
        out[((size_t)(b*8 + k0)*254 + y)*254 + x] = s0*(fmaxf(a0,0.f) - mm[k0]) + bb[k0];
        out[((size_t)(b*8 + k1)*254 + y)*254 + x] = s1*(fmaxf(a1,0.f) - mm[k1]) + bb[k1];
    }
}

// ---------------- conv2: scalar f32x2 path with fused maxpool+bn (MODE 3 only) ----------------
template<int CI, int CO, int HIN, int WIN>
__global__ __launch_bounds__(256, 3)
void conv2s_k(const float* __restrict__ gin, const float* __restrict__ gw,
              const float* __restrict__ gb,
              const float* __restrict__ bng, const float* __restrict__ bnb,
              const float* __restrict__ bnm, const float* __restrict__ bnv,
              float* __restrict__ gout) {
    constexpr int WOUT = WIN - 2, HOUT = HIN - 2;
    constexpr int TW   = 32;
    constexpr int NCOG = CO / 8;            // 2
    constexpr int SPR  = TW / 4;            // 8
    constexpr int ROWS = 256 / (NCOG*SPR);  // 16
    constexpr int CC   = 8;
    constexpr int NCH  = CI / CC;
    constexpr int STR  = TW + 4;
    constexpr int LW   = TW + 2;
    constexpr int IROWS = ROWS + 2;

    __shared__ __align__(16) float in_s[CC*IROWS*STR];
    __shared__ __align__(16) float w_s[9*CI*CO];

    int tid = threadIdx.x;
    int cog  = tid % NCOG;
    int slot = tid / NCOG;
    int yl = slot / SPR;
    int xo = (slot % SPR) * 4;
    int ox0 = blockIdx.x * TW, oy0 = blockIdx.y * ROWS;
    int b = blockIdx.z;

    for (int idx = tid; idx < 9*CI*CO; idx += 256) w_s[idx] = gw[idx];

    u64t acc[4][4];
#pragma unroll
    for (int m = 0; m < 4; m++)
#pragma unroll
        for (int p = 0; p < 4; p++) acc[m][p] = 0ull;

    for (int cc = 0; cc < NCH; cc++) {
        __syncthreads();
        for (int idx = tid; idx < CC*IROWS*LW; idx += 256) {
            int ci = idx / (IROWS*LW), rem = idx % (IROWS*LW);
            int yy = rem / LW, xx = rem % LW;
            int gy = oy0 + yy, gx = ox0 + xx;
            float v = 0.f;
            if (gy < HIN && gx < WIN)
                v = gin[((size_t)(b*CI + cc*CC + ci)*HIN + gy)*WIN + gx];
            in_s[ci*(IROWS*STR) + yy*STR + xx] = v;
        }
        __syncthreads();
#pragma unroll 2
        for (int ci = 0; ci < CC; ci++) {
            const int cig = cc*CC + ci;
#pragma unroll
            for (int dy = 0; dy < 3; dy++) {
                const float* ip = in_s + ci*(IROWS*STR) + (yl+dy)*STR + xo;
                float4 ra = *(const float4*)(ip);
                float2 rb = *(const float2*)(ip+4);
                u64t pv[6];
                pv[0] = pk2(ra.x, ra.x); pv[1] = pk2(ra.y, ra.y);
                pv[2] = pk2(ra.z, ra.z); pv[3] = pk2(ra.w, ra.w);
                pv[4] = pk2(rb.x, rb.x); pv[5] = pk2(rb.y, rb.y);
#pragma unroll
                for (int dx = 0; dx < 3; dx++) {
                    const u64t* wq = (const u64t*)(w_s + (dy*3+dx)*(CI*CO) + cig*CO + cog*8);
                    u64t w0 = wq[0], w1 = wq[1], w2 = wq[2], w3 = wq[3];
#pragma unroll
                    for (int m = 0; m < 4; m++) {
                        fma2(acc[m][0], pv[dx+m], w0);
                        fma2(acc[m][1], pv[dx+m], w1);
                        fma2(acc[m][2], pv[dx+m], w2);
                        fma2(acc[m][3], pv[dx+m], w3);
                    }
                }
            }
        }
    }

    float r[4][8];
    float bia[8];
#pragma unroll
    for (int k = 0; k < 8; k++) bia[k] = gb[cog*8 + k];
#pragma unroll
    for (int m = 0; m < 4; m++)
#pragma unroll
        for (int p = 0; p < 4; p++) {
            float a0, a1; upk2(acc[m][p], a0, a1);
            r[m][2*p]   = fmaxf(a0 + bia[2*p],   0.f);
            r[m][2*p+1] = fmaxf(a1 + bia[2*p+1], 0.f);
        }

    int oy = oy0 + yl;
    float xp[2][8];
#pragma unroll
    for (int q = 0; q < 2; q++)
#pragma unroll
        for (int k = 0; k < 8; k++)
            xp[q][k] = fmaxf(r[2*q][k], r[2*q+1][k]);
    int py = yl >> 1;
    int pxb = xo >> 1;
    float* pool_s = in_s;
    __syncthreads();
    if (yl & 1) {
#pragma unroll
        for (int q = 0; q < 2; q++)
#pragma unroll
            for (int k = 0; k < 8; k++)
                pool_s[((py*(TW/2) + pxb + q)*CO) + cog*8 + k] = xp[q][k];
    }
    __syncthreads();
    if (!(yl & 1)) {
        int gy_p = oy >> 1;
        if (gy_p < HOUT/2) {
#pragma unroll
            for (int q = 0; q < 2; q++) {
                int gx_p = ((ox0 + xo) >> 1) + q;
                if (gx_p < WOUT/2) {
#pragma unroll
                    for (int k = 0; k < 8; k++) {
                        int co = cog*8 + k;
                        float v = fmaxf(xp[q][k],
                            pool_s[((py*(TW/2) + pxb + q)*CO) + co]);
                        float sc = bng[co] * rsqrtf(bnv[co] + BN_EPS);
                        v = sc*(v - bnm[co]) + bnb[co];
                        gout[((size_t)(b*CO + co)*(HOUT/2) + gy_p)*(WOUT/2) + gx_p] = v;
                    }
                }
            }
        }
    }
}

// ---------------- tensor-core tf32 conv (conv3 / conv4), CO=32 ----------------
// CTA: 8 warps; warp w owns output row y0+w, 32 x-positions (2 m16 frags), all 32 co (4 n8).
// K sliced as (tap, ci-block-of-8). Input smem: ci-plane 10x36 (tf32). Weights: 40-stride pad.
// MODE 1: store bn(relu(conv+b))   MODE 2: global atomic max of relu(conv+b)
template<int CI, int HIN, int WIN, int MODE>
__global__ __launch_bounds__(256)
void tconv_k(const float* __restrict__ gin, const float* __restrict__ gw,
             const float* __restrict__ gb,
             const float* __restrict__ bng, const float* __restrict__ bnb,
             const float* __restrict__ bnm, const float* __restrict__ bnv,
             float* __restrict__ gout) {
    constexpr int CO = 32;
    constexpr int HOUT = HIN - 2, WOUT = WIN - 2;
    constexpr int CC  = 16;
    constexpr int NCH = CI / CC;
    constexpr int STR = 36, PLANE = 10*STR;   // per-ci input plane
    constexpr int WSTR = 40;                   // padded co-stride (bank-conflict-free B frags)

    __shared__ unsigned in_s[CC*PLANE];        // tf32 bits
    __shared__ unsigned w_s[9*CC*WSTR];
    __shared__ float smax[CO];

    int tid = threadIdx.x;
    int warp = tid >> 5, lane = tid & 31;
    int kq = lane & 3, nr = lane >> 2;        // threadID_in_group, groupID
    int ox0 = blockIdx.x * 32, oy0 = blockIdx.y * 8;
    int b = blockIdx.z;

    if (MODE == 2 && tid < CO) smax[tid] = 0.f;

    float acc[2][4][4];
#pragma unroll
    for (int j = 0; j < 2; j++)
#pragma unroll
        for (int nb = 0; nb < 4; nb++)
#pragma unroll
            for (int q = 0; q < 4; q++) acc[j][nb][q] = 0.f;

    for (int cc = 0; cc < NCH; cc++) {
        __syncthreads();
        // input tile: CC x 10 x 34, tf32-converted
        for (int idx = tid; idx < CC*10*34; idx += 256) {
            int ci = idx / 340, rem = idx % 340;
            int yy = rem / 34, xx = rem % 34;
            int gy = oy0 + yy, gx = ox0 + xx;
            float v = 0.f;
            if (gy < HIN && gx < WIN)
                v = gin[((size_t)(b*CI + cc*CC + ci)*HIN + gy)*WIN + gx];
            in_s[ci*PLANE + yy*STR + xx] = tf32r(v);
        }
        // weights: [tap][ci][co] with WSTR pad
        for (int idx = tid; idx < 9*CC*CO; idx += 256) {
            int tap = idx / (CC*CO), r = idx % (CC*CO);
            int ci = r / CO, co = r % CO;
            w_s[tap*(CC*WSTR) + ci*WSTR + co] =
                tf32r(gw[tap*(CI*CO) + (cc*CC + ci)*CO + co]);
        }
        __syncthreads();
#pragma unroll
        for (int tap = 0; tap < 9; tap++) {
            const int dy = tap/3, dx = tap%3;
#pragma unroll
            for (int cib = 0; cib < CC/8; cib++) {
                // B fragments for 4 n-blocks
                const unsigned* wb = w_s + tap*(CC*WSTR) + (cib*8)*WSTR;
                unsigned bf[4][2];
#pragma unroll
                for (int nb = 0; nb < 4; nb++) {
                    bf[nb][0] = wb[kq*WSTR + nb*8 + nr];
                    bf[nb][1] = wb[(kq+4)*WSTR + nb*8 + nr];
                }
                const unsigned* ia = in_s + (cib*8 + kq)*PLANE + (warp+dy)*STR + dx + nr;
#pragma unroll
                for (int j = 0; j < 2; j++) {
                    unsigned a0 = ia[j*16];
                    unsigned a1 = ia[j*16 + 8];
                    unsigned a2 = ia[j*16 + 4*PLANE];
                    unsigned a3 = ia[j*16 + 4*PLANE + 8];
#pragma unroll
                    for (int nb = 0; nb < 4; nb++)
                        MMA_TF32(acc[j][nb], a0, a1, a2, a3, bf[nb][0], bf[nb][1]);
                }
            }
        }
    }

    // epilogue: thread holds (y=oy0+warp; x = ox0+16j+nr (+8); co = nb*8+2kq (+1))
    int y = oy0 + warp;
    float biA[4], biB[4];
#pragma unroll
    for (int nb = 0; nb < 4; nb++) {
        biA[nb] = gb[nb*8 + 2*kq];
        biB[nb] = gb[nb*8 + 2*kq + 1];
    }

    if (MODE == 2) {
        float lm[4][2];
#pragma unroll
        for (int nb = 0; nb < 4; nb++) { lm[nb][0] = 0.f; lm[nb][1] = 0.f; }
        if (y < HOUT) {
#pragma unroll
            for (int j = 0; j < 2; j++) {
                int xA = ox0 + j*16 + nr;
                int xB = xA + 8;
#pragma unroll
                for (int nb = 0; nb < 4; nb++) {
                    if (xA < WOUT) {
                        lm[nb][0] = fmaxf(lm[nb][0], acc[j][nb][0] + biA[nb]);
                        lm[nb][1] = fmaxf(lm[nb][1], acc[j][nb][1] + biB[nb]);
                    }
                    if (xB < WOUT) {
                        lm[nb][0] = fmaxf(lm[nb][0], acc[j][nb][2] + biA[nb]);
                        lm[nb][1] = fmaxf(lm[nb][1], acc[j][nb][3] + biB[nb]);
                    }
                }
            }
        }
#pragma unroll
        for (int nb = 0; nb < 4; nb++) {
            atomicMax((int*)&smax[nb*8 + 2*kq],     __float_as_int(fmaxf(lm[nb][0], 0.f)));
            atomicMax((int*)&smax[nb*8 + 2*kq + 1], __float_as_int(fmaxf(lm[nb][1], 0.f)));
        }
        __syncthreads();
        if (tid < CO)
            atomicMax((int*)&gout[b*CO + tid], __float_as_int(smax[tid]));
    } else {
        if (y < HOUT) {
#pragma unroll
            for (int nb = 0; nb < 4; nb++) {
                int coA = nb*8 + 2*kq, coB = coA + 1;
                float scA = bng[coA] * rsqrtf(bnv[coA] + BN_EPS);
                float scB = bng[coB] * rsqrtf(bnv[coB] + BN_EPS);
                float sbA = bnb[coA], sbB = bnb[coB];
                float smA = bnm[coA], smB = bnm[coB];
                float* pA = gout + ((size_t)(b*CO + coA)*HOUT + y)*WOUT;
                float* pB = gout + ((size_t)(b*CO + coB)*HOUT + y)*WOUT;
#pragma unroll
                for (int j = 0; j < 2; j++) {
                    int xA = ox0 + j*16 + nr;
                    int xB = xA + 8;
                    if (xA < WOUT) {
                        pA[xA] = scA*(fmaxf(acc[j][nb][0] + biA[nb], 0.f) - smA) + sbA;
                        pB[xA] = scB*(fmaxf(acc[j][nb][1] + biB[nb], 0.f) - smB) + sbB;
                    }
                    if (xB < WOUT) {
                        pA[xB] = scA*(fmaxf(acc[j][nb][2] + biA[nb], 0.f) - smA) + sbA;
                        pB[xB] = scB*(fmaxf(acc[j][nb][3] + biB[nb], 0.f) - smB) + sbB;
                    }
                }
            }
        }
    }
}

// ---------------- dense ----------------
__global__ void dense_k(const float* __restrict__ gm, const float* __restrict__ dw,
                        const float* __restrict__ db, float* __restrict__ h,
                        float* __restrict__ out_tail) {
    int b = threadIdx.x;
    if (b >= B) return;
    float s = db[0];
#pragma unroll
    for (int c = 0; c < 32; c++) s = fmaf(gm[b*32 + c], dw[c], s);
    h[b] = s;
    out_tail[b] = s;
}

// ---------------- geodesic reconstruction: 5 fused steps, 64x64 tile ----------------
#define RK 5
#define RT 64
#define RS (RT + 2*RK)
#define RCELL (RS*RS)
#define RNIT ((RCELL + 255)/256)
template<bool INIT>
__global__ __launch_bounds__(256)
void recon_k(const float* __restrict__ src, const float* __restrict__ mask,
             const float* __restrict__ h, float* __restrict__ dst) {
    __shared__ float sm[2][RCELL];
    int t = threadIdx.x;
    int ox = blockIdx.x*RT - RK;
    int oy = blockIdx.y*RT - RK;
    const size_t boff = (size_t)blockIdx.z*H0*W0;
    const float hv = INIT ? h[blockIdx.z] : 0.f;

    float mk[RNIT];
    bool  inter[RNIT];
#pragma unroll
    for (int k = 0; k < RNIT; k++) {
        int i = t + k*256;
        float sv = -CUDART_INF_F, mv = -CUDART_INF_F;
        bool it = false;
        if (i < RCELL) {
            int ly = i / RS, lx = i % RS;
            int gy = oy + ly, gx = ox + lx;
            if (gy >= 0 && gy < H0 && gx >= 0 && gx < W0) {
                mv = mask[boff + gy*W0 + gx];
                sv = INIT ? (mv - hv) : src[boff + gy*W0 + gx];
            }
            sm[0][i] = sv;
            it = (ly > 0 && ly < RS-1 && lx > 0 && lx < RS-1);
        }
        mk[k] = mv;
        inter[k] = it;
    }
    __syncthreads();
    int cur = 0;
#pragma unroll
    for (int step = 0; step < RK; step++) {
#pragma unroll
        for (int k = 0; k < RNIT; k++) {
            int i = t + k*256;
            if (i < RCELL) {
                float v;
                if (inter[k]) {
                    const float* s0 = &sm[cur][i];
                    float a = fmaxf(fmaxf(s0[-RS-1], s0[-RS]), s0[-RS+1]);
                    float c = fmaxf(fmaxf(s0[-1],    s0[0]),   s0[1]);
                    float d = fmaxf(fmaxf(s0[RS-1],  s0[RS]),  s0[RS+1]);
                    v = fminf(fmaxf(fmaxf(a, c), d), mk[k]);
                } else {
                    v = sm[cur][i];
                }
                sm[1-cur][i] = v;
            }
        }
        __syncthreads();
        cur ^= 1;
    }
    int tx = t & 63, tyq = t >> 6;
#pragma unroll
    for (int k = 0; k < 16; k++) {
        int r = tyq + 4*k;
        dst[boff + (size_t)(oy + RK + r)*W0 + (ox + RK + tx)] =
            sm[cur][(r + RK)*RS + (tx + RK)];
    }
}

// ---------------- launch ----------------
extern "C" void kernel_launch(void* const* d_in, const int* in_sizes, int n_in,
                              void* d_out, int out_size) {
    const float* x    = (const float*)d_in[0];
    const float* ko   = (const float*)d_in[1];
    const float* kc   = (const float*)d_in[2];
    const float* w1   = (const float*)d_in[3];
    const float* b1   = (const float*)d_in[4];
    const float* w2   = (const float*)d_in[5];
    const float* b2   = (const float*)d_in[6];
    const float* w3   = (const float*)d_in[7];
    const float* b3   = (const float*)d_in[8];
    const float* w4   = (const float*)d_in[9];
    const float* b4   = (const float*)d_in[10];
    const float* bn1g = (const float*)d_in[11];
    const float* bn1b = (const float*)d_in[12];
    const float* bn1m = (const float*)d_in[13];
    const float* bn1v = (const float*)d_in[14];
    const float* bn2g = (const float*)d_in[15];
    const float* bn2b = (const float*)d_in[16];
    const float* bn2m = (const float*)d_in[17];
    const float* bn2v = (const float*)d_in[18];
    const float* bn3g = (const float*)d_in[19];
    const float* bn3b = (const float*)d_in[20];
    const float* bn3m = (const float*)d_in[21];
    const float* bn3v = (const float*)d_in[22];
    const float* dw   = (const float*)d_in[23];
    const float* db   = (const float*)d_in[24];
    float* out = (float*)d_out;

    float *MA, *MB, *XC, *Y1, *Y2, *Y3, *GM, *HH;
    cudaGetSymbolAddress((void**)&MA, g_MA);
    cudaGetSymbolAddress((void**)&MB, g_MB);
    cudaGetSymbolAddress((void**)&XC, g_XC);
    cudaGetSymbolAddress((void**)&Y1, g_Y1);
    cudaGetSymbolAddress((void**)&Y2, g_Y2);
    cudaGetSymbolAddress((void**)&Y3, g_Y3);
    cudaGetSymbolAddress((void**)&GM, g_GM);
    cudaGetSymbolAddress((void**)&HH, g_H);

    // fused morphology -> XC
    morph4_k<<<dim3(4, 4, B), 256>>>(x, XC, ko, kc);

    // CNN
    conv1_k<<<dim3(254, B), 256>>>(XC, w1, b1, bn1g, bn1b, bn1m, bn1v, Y1);
    conv2s_k<8, 16, 254, 254><<<dim3(8, 16, B), 256>>>(
        Y1, w2, b2, bn2g, bn2b, bn2m, bn2v, Y2);
    tconv_k<16, 126, 126, 1><<<dim3(4, 16, B), 256>>>(
        Y2, w3, b3, bn3g, bn3b, bn3m, bn3v, Y3);
    cudaMemsetAsync(GM, 0, B*32*sizeof(float));
    tconv_k<32, 124, 124, 2><<<dim3(4, 16, B), 256>>>(
        Y3, w4, b4, nullptr, nullptr, nullptr, nullptr, GM);
    dense_k<<<1, 32>>>(GM, dw, db, HH, out + (size_t)NPIX);

    // h-maxima: 50 steps = 10 launches of 5 fused steps (first fuses marker init)
    recon_k<true><<<dim3(4, 4, B), 256>>>(XC, XC, HH, MB);
    for (int l = 1; l < 10; l++) {
        float* srcp = (l & 1) ? MB : MA;
        float* dstp = (l == 9) ? out : ((l & 1) ? MA : MB);
        recon_k<false><<<dim3(4, 4, B), 256>>>(srcp, XC, nullptr, dstp);
    }
}

// round 7
// speedup vs baseline: 5.1425x; 1.0991x over previous
#include <cuda_runtime.h>
#include <math_constants.h>

#define B 32
#define H0 256
#define W0 256
#define NPIX (B*H0*W0)
#define BN_EPS 1e-3f

typedef unsigned long long u64t;

__device__ __forceinline__ u64t pk2(float a, float b) {
    u64t r; asm("mov.b64 %0,{%1,%2};" : "=l"(r) : "f"(a), "f"(b)); return r;
}
__device__ __forceinline__ void upk2(u64t v, float& a, float& b) {
    asm("mov.b64 {%0,%1},%2;" : "=f"(a), "=f"(b) : "l"(v));
}
__device__ __forceinline__ void fma2(u64t& d, u64t a, u64t b) {
    asm("fma.rn.f32x2 %0,%1,%2,%0;" : "+l"(d) : "l"(a), "l"(b));
}
__device__ __forceinline__ unsigned tf32r(float v) {
    unsigned r; asm("cvt.rna.tf32.f32 %0,%1;" : "=r"(r) : "f"(v)); return r;
}
#define MMA_TF32(d, a0,a1,a2,a3, b0,b1) \
    asm volatile("mma.sync.aligned.m16n8k8.row.col.f32.tf32.tf32.f32 " \
        "{%0,%1,%2,%3},{%4,%5,%6,%7},{%8,%9},{%0,%1,%2,%3};" \
        : "+f"((d)[0]),"+f"((d)[1]),"+f"((d)[2]),"+f"((d)[3]) \
        : "r"(a0),"r"(a1),"r"(a2),"r"(a3),"r"(b0),"r"(b1))

// ---------------- scratch ----------------
__device__ float g_MA[NPIX];
__device__ float g_MB[NPIX];
__device__ float g_XC[NPIX];
__device__ float g_Y1[(size_t)B*8*254*254];
__device__ float g_Y2[(size_t)B*16*126*126];
__device__ float g_Y3[(size_t)B*32*124*124];
__device__ float g_GM[B*32];
__device__ float g_H[B];

// ---------------- fused 4-pass morphology: E(ko),D(ko),D(kc),E(kc), halo 4 ----------------
#define MT 64
#define MHL 4
#define MS (MT + 2*MHL)
#define MCELL (MS*MS)
#define MNIT ((MCELL + 255)/256)
__global__ __launch_bounds__(256)
void morph4_k(const float* __restrict__ x, float* __restrict__ xc,
              const float* __restrict__ ko, const float* __restrict__ kc) {
    __shared__ float sm[2][MCELL];
    __shared__ float sk[18];
    int t = threadIdx.x;
    if (t < 18) sk[t] = (t < 9) ? ko[t] : kc[t - 9];
    int ox = blockIdx.x*MT - MHL;
    int oy = blockIdx.y*MT - MHL;
    const size_t boff = (size_t)blockIdx.z*H0*W0;

    bool inb[MNIT], inter[MNIT];
#pragma unroll
    for (int k = 0; k < MNIT; k++) {
        int i = t + k*256;
        bool ib = false, it = false;
        if (i < MCELL) {
            int ly = i / MS, lx = i % MS;
            int gy = oy + ly, gx = ox + lx;
            ib = (gy >= 0 && gy < H0 && gx >= 0 && gx < W0);
            sm[0][i] = ib ? x[boff + gy*W0 + gx] : CUDART_INF_F;
            it = (ly > 0 && ly < MS-1 && lx > 0 && lx < MS-1);
        }
        inb[k] = ib; inter[k] = it;
    }
    __syncthreads();
    int cur = 0;
#pragma unroll
    for (int op = 0; op < 4; op++) {
        const bool ero = (op == 0 || op == 3);
        const int koff = (op < 2) ? 0 : 9;
        const float nextpad = (op >= 2) ? CUDART_INF_F : -CUDART_INF_F;
#pragma unroll
        for (int k = 0; k < MNIT; k++) {
            int i = t + k*256;
            if (i < MCELL) {
                float v;
                if (!inb[k]) {
                    v = nextpad;
                } else if (inter[k]) {
                    const float* s0 = &sm[cur][i];
                    if (ero) {
                        float m = s0[-MS-1] - sk[koff + 8];
                        m = fminf(m, s0[-MS  ] - sk[koff + 7]);
                        m = fminf(m, s0[-MS+1] - sk[koff + 6]);
                        m = fminf(m, s0[-1]    - sk[koff + 5]);
                        m = fminf(m, s0[0]     - sk[koff + 4]);
                        m = fminf(m, s0[1]     - sk[koff + 3]);
                        m = fminf(m, s0[MS-1]  - sk[koff + 2]);
                        m = fminf(m, s0[MS  ]  - sk[koff + 1]);
                        m = fminf(m, s0[MS+1]  - sk[koff + 0]);
                        v = m;
                    } else {
                        float m = s0[-MS-1] + sk[koff + 0];
                        m = fmaxf(m, s0[-MS  ] + sk[koff + 1]);
                        m = fmaxf(m, s0[-MS+1] + sk[koff + 2]);
                        m = fmaxf(m, s0[-1]    + sk[koff + 3]);
                        m = fmaxf(m, s0[0]     + sk[koff + 4]);
                        m = fmaxf(m, s0[1]     + sk[koff + 5]);
                        m = fmaxf(m, s0[MS-1]  + sk[koff + 6]);
                        m = fmaxf(m, s0[MS  ]  + sk[koff + 7]);
                        m = fmaxf(m, s0[MS+1]  + sk[koff + 8]);
                        v = m;
                    }
                } else {
                    v = sm[cur][i];
                }
                sm[1-cur][i] = v;
            }
        }
        __syncthreads();
        cur ^= 1;
    }
    int tx = t & 63, tyq = t >> 6;
#pragma unroll
    for (int k = 0; k < 16; k++) {
        int r = tyq + 4*k;
        xc[boff + (size_t)(oy + MHL + r)*W0 + (ox + MHL + tx)] =
            sm[cur][(r + MHL)*MS + (tx + MHL)];
    }
}

// ---------------- conv1 (1->8) + relu + bn1 ----------------
__global__ void conv1_k(const float* __restrict__ xc, const float* __restrict__ w,
                        const float* __restrict__ bias,
                        const float* __restrict__ gg, const float* __restrict__ bb,
                        const float* __restrict__ mm, const float* __restrict__ vv,
                        float* __restrict__ out) {
    __shared__ float ws[72];
    int t = threadIdx.x;
    if (t < 72) ws[t] = w[t];
    __syncthreads();
    int y = blockIdx.x, b = blockIdx.y;
    int x = t;
    if (x >= 254) return;
    const float* base = xc + ((size_t)b*H0 + y)*W0 + x;
    u64t acc[4];
#pragma unroll
    for (int p = 0; p < 4; p++) acc[p] = pk2(bias[2*p], bias[2*p+1]);
#pragma unroll
    for (int tap = 0; tap < 9; tap++) {
        float v = base[(tap/3)*W0 + (tap%3)];
        u64t pv = pk2(v, v);
        const u64t* wq = (const u64t*)(ws + tap*8);
#pragma unroll
        for (int p = 0; p < 4; p++) fma2(acc[p], pv, wq[p]);
    }
#pragma unroll
    for (int p = 0; p < 4; p++) {
        float a0, a1; upk2(acc[p], a0, a1);
        int k0 = 2*p, k1 = 2*p+1;
        float s0 = gg[k0] * rsqrtf(vv[k0] + BN_EPS);
        float s1 = gg[k1] * rsqrtf(vv[k1] + BN_EPS);
        out[((size_t)(b*8 + k0)*254 + y)*254 + x] = s0*(fmaxf(a0,0.f) - mm[k0]) + bb[k0];
        out[((size_t)(b*8 + k1)*254 + y)*254 + x] = s1*(fmaxf(a1,0.f) - mm[k1]) + bb[k1];
    }
}

// ================= tensor tf32 conv, TW=64 (4 m16 frags / row / warp) =================
// common geometry: 8 warps, warp w -> output row oy0+w; x covers ox0..ox0+63.
#define TSTR   68
#define TPLANE 680
#define TWSTR  40

// ---------------- conv3/conv4: CO=32, dynamic smem ----------------
// MODE 1: store bn(relu(conv+b))   MODE 2: global atomic max of relu(conv+b)
template<int CI, int HIN, int WIN, int MODE>
__global__ __launch_bounds__(256, 2)
void tconv_k(const float* __restrict__ gin, const float* __restrict__ gw,
             const float* __restrict__ gb,
             const float* __restrict__ bng, const float* __restrict__ bnb,
             const float* __restrict__ bnm, const float* __restrict__ bnv,
             float* __restrict__ gout) {
    constexpr int CO = 32;
    constexpr int HOUT = HIN - 2, WOUT = WIN - 2;
    constexpr int CC  = 16;
    constexpr int NCH = CI / CC;
    constexpr int LW  = 66;

    extern __shared__ unsigned shm[];
    unsigned* in_s = shm;                         // CC*TPLANE = 10880
    unsigned* w_s  = shm + CC*TPLANE;             // 9*CC*TWSTR = 5760
    float* smax    = (float*)(w_s + 9*CC*TWSTR);  // 32

    int tid = threadIdx.x;
    int warp = tid >> 5, lane = tid & 31;
    int kq = lane & 3, nr = lane >> 2;
    int ox0 = blockIdx.x * 64, oy0 = blockIdx.y * 8;
    int b = blockIdx.z;

    if (MODE == 2 && tid < CO) smax[tid] = 0.f;

    float acc[4][4][4];
#pragma unroll
    for (int j = 0; j < 4; j++)
#pragma unroll
        for (int nb = 0; nb < 4; nb++)
#pragma unroll
            for (int q = 0; q < 4; q++) acc[j][nb][q] = 0.f;

    for (int cc = 0; cc < NCH; cc++) {
        __syncthreads();
        for (int idx = tid; idx < CC*10*LW; idx += 256) {
            int ci = idx / (10*LW), rem = idx % (10*LW);
            int yy = rem / LW, xx = rem % LW;
            int gy = oy0 + yy, gx = ox0 + xx;
            float v = 0.f;
            if (gy < HIN && gx < WIN)
                v = gin[((size_t)(b*CI + cc*CC + ci)*HIN + gy)*WIN + gx];
            in_s[ci*TPLANE + yy*TSTR + xx] = tf32r(v);
        }
        for (int idx = tid; idx < 9*CC*CO; idx += 256) {
            int tap = idx / (CC*CO), r = idx % (CC*CO);
            int ci = r / CO, co = r % CO;
            w_s[tap*(CC*TWSTR) + ci*TWSTR + co] =
                tf32r(gw[tap*(CI*CO) + (cc*CC + ci)*CO + co]);
        }
        __syncthreads();
#pragma unroll
        for (int tap = 0; tap < 9; tap++) {
            const int dy = tap/3, dx = tap%3;
#pragma unroll
            for (int cib = 0; cib < CC/8; cib++) {
                const unsigned* wb = w_s + tap*(CC*TWSTR) + (cib*8)*TWSTR;
                unsigned bf[4][2];
#pragma unroll
                for (int nb = 0; nb < 4; nb++) {
                    bf[nb][0] = wb[kq*TWSTR + nb*8 + nr];
                    bf[nb][1] = wb[(kq+4)*TWSTR + nb*8 + nr];
                }
                const unsigned* ia = in_s + (cib*8 + kq)*TPLANE + (warp+dy)*TSTR + dx + nr;
#pragma unroll
                for (int j = 0; j < 4; j++) {
                    unsigned a0 = ia[j*16];
                    unsigned a1 = ia[j*16 + 8];
                    unsigned a2 = ia[j*16 + 4*TPLANE];
                    unsigned a3 = ia[j*16 + 4*TPLANE + 8];
#pragma unroll
                    for (int nb = 0; nb < 4; nb++)
                        MMA_TF32(acc[j][nb], a0, a1, a2, a3, bf[nb][0], bf[nb][1]);
                }
            }
        }
    }

    int y = oy0 + warp;
    float biA[4], biB[4];
#pragma unroll
    for (int nb = 0; nb < 4; nb++) {
        biA[nb] = gb[nb*8 + 2*kq];
        biB[nb] = gb[nb*8 + 2*kq + 1];
    }

    if (MODE == 2) {
        float lm[4][2];
#pragma unroll
        for (int nb = 0; nb < 4; nb++) { lm[nb][0] = 0.f; lm[nb][1] = 0.f; }
        if (y < HOUT) {
#pragma unroll
            for (int j = 0; j < 4; j++) {
                int xA = ox0 + j*16 + nr;
                int xB = xA + 8;
#pragma unroll
                for (int nb = 0; nb < 4; nb++) {
                    if (xA < WOUT) {
                        lm[nb][0] = fmaxf(lm[nb][0], acc[j][nb][0] + biA[nb]);
                        lm[nb][1] = fmaxf(lm[nb][1], acc[j][nb][1] + biB[nb]);
                    }
                    if (xB < WOUT) {
                        lm[nb][0] = fmaxf(lm[nb][0], acc[j][nb][2] + biA[nb]);
                        lm[nb][1] = fmaxf(lm[nb][1], acc[j][nb][3] + biB[nb]);
                    }
                }
            }
        }
#pragma unroll
        for (int nb = 0; nb < 4; nb++) {
            atomicMax((int*)&smax[nb*8 + 2*kq],     __float_as_int(fmaxf(lm[nb][0], 0.f)));
            atomicMax((int*)&smax[nb*8 + 2*kq + 1], __float_as_int(fmaxf(lm[nb][1], 0.f)));
        }
        __syncthreads();
        if (tid < CO)
            atomicMax((int*)&gout[b*CO + tid], __float_as_int(smax[tid]));
    } else {
        if (y < HOUT) {
#pragma unroll
            for (int nb = 0; nb < 4; nb++) {
                int coA = nb*8 + 2*kq, coB = coA + 1;
                float scA = bng[coA] * rsqrtf(bnv[coA] + BN_EPS);
                float scB = bng[coB] * rsqrtf(bnv[coB] + BN_EPS);
                float sbA = bnb[coA], sbB = bnb[coB];
                float smA = bnm[coA], smB = bnm[coB];
                float* pA = gout + ((size_t)(b*CO + coA)*HOUT + y)*WOUT;
                float* pB = gout + ((size_t)(b*CO + coB)*HOUT + y)*WOUT;
#pragma unroll
                for (int j = 0; j < 4; j++) {
                    int xA = ox0 + j*16 + nr;
                    int xB = xA + 8;
                    if (xA < WOUT) {
                        pA[xA] = scA*(fmaxf(acc[j][nb][0] + biA[nb], 0.f) - smA) + sbA;
                        pB[xA] = scB*(fmaxf(acc[j][nb][1] + biB[nb], 0.f) - smB) + sbB;
                    }
                    if (xB < WOUT) {
                        pA[xB] = scA*(fmaxf(acc[j][nb][2] + biA[nb], 0.f) - smA) + sbA;
                        pB[xB] = scB*(fmaxf(acc[j][nb][3] + biB[nb], 0.f) - smB) + sbB;
                    }
                }
            }
        }
    }
}
constexpr int TCONV_SHM = (16*TPLANE + 9*16*TWSTR + 32) * 4;

// ---------------- conv2 tensor: CI=8, CO=16, fused maxpool2+bn ----------------
__global__ __launch_bounds__(256)
void tconv2_k(const float* __restrict__ gin, const float* __restrict__ gw,
              const float* __restrict__ gb,
              const float* __restrict__ bng, const float* __restrict__ bnb,
              const float* __restrict__ bnm, const float* __restrict__ bnv,
              float* __restrict__ gout) {
    constexpr int CI = 8, CO = 16;
    constexpr int HIN = 254, WIN = 254;
    constexpr int HOUT = 252, WOUT = 252;
    constexpr int LW = 66;

    __shared__ unsigned shm2[CI*TPLANE + 9*CI*TWSTR];  // 5440 + 2880 = 8320
    unsigned* in_s = shm2;
    unsigned* w_s  = shm2 + CI*TPLANE;
    float* pool_s  = (float*)shm2;                     // alias after compute (needs 8192)

    int tid = threadIdx.x;
    int warp = tid >> 5, lane = tid & 31;
    int kq = lane & 3, nr = lane >> 2;
    int ox0 = blockIdx.x * 64, oy0 = blockIdx.y * 8;
    int b = blockIdx.z;

    float acc[4][2][4];
#pragma unroll
    for (int j = 0; j < 4; j++)
#pragma unroll
        for (int nb = 0; nb < 2; nb++)
#pragma unroll
            for (int q = 0; q < 4; q++) acc[j][nb][q] = 0.f;

    for (int idx = tid; idx < CI*10*LW; idx += 256) {
        int ci = idx / (10*LW), rem = idx % (10*LW);
        int yy = rem / LW, xx = rem % LW;
        int gy = oy0 + yy, gx = ox0 + xx;
        float v = 0.f;
        if (gy < HIN && gx < WIN)
            v = gin[((size_t)(b*CI + ci)*HIN + gy)*WIN + gx];
        in_s[ci*TPLANE + yy*TSTR + xx] = tf32r(v);
    }
    for (int idx = tid; idx < 9*CI*CO; idx += 256) {
        int tap = idx / (CI*CO), r = idx % (CI*CO);
        int ci = r / CO, co = r % CO;
        w_s[tap*(CI*TWSTR) + ci*TWSTR + co] = tf32r(gw[idx]);
    }
    __syncthreads();
#pragma unroll
    for (int tap = 0; tap < 9; tap++) {
        const int dy = tap/3, dx = tap%3;
        const unsigned* wb = w_s + tap*(CI*TWSTR);
        unsigned bf[2][2];
#pragma unroll
        for (int nb = 0; nb < 2; nb++) {
            bf[nb][0] = wb[kq*TWSTR + nb*8 + nr];
            bf[nb][1] = wb[(kq+4)*TWSTR + nb*8 + nr];
        }
        const unsigned* ia = in_s + kq*TPLANE + (warp+dy)*TSTR + dx + nr;
#pragma unroll
        for (int j = 0; j < 4; j++) {
            unsigned a0 = ia[j*16];
            unsigned a1 = ia[j*16 + 8];
            unsigned a2 = ia[j*16 + 4*TPLANE];
            unsigned a3 = ia[j*16 + 4*TPLANE + 8];
#pragma unroll
            for (int nb = 0; nb < 2; nb++)
                MMA_TF32(acc[j][nb], a0, a1, a2, a3, bf[nb][0], bf[nb][1]);
        }
    }

    // relu(conv+b) -> pool_s[y(8)][x(64)][co(16)]
    float biA[2], biB[2];
#pragma unroll
    for (int nb = 0; nb < 2; nb++) {
        biA[nb] = gb[nb*8 + 2*kq];
        biB[nb] = gb[nb*8 + 2*kq + 1];
    }
    __syncthreads();   // done reading in_s/w_s
#pragma unroll
    for (int j = 0; j < 4; j++) {
        int xA = j*16 + nr, xB = xA + 8;
#pragma unroll
        for (int nb = 0; nb < 2; nb++) {
            int coA = nb*8 + 2*kq, coB = coA + 1;
            pool_s[warp*1024 + xA*16 + coA] = fmaxf(acc[j][nb][0] + biA[nb], 0.f);
            pool_s[warp*1024 + xA*16 + coB] = fmaxf(acc[j][nb][1] + biB[nb], 0.f);
            pool_s[warp*1024 + xB*16 + coA] = fmaxf(acc[j][nb][2] + biA[nb], 0.f);
            pool_s[warp*1024 + xB*16 + coB] = fmaxf(acc[j][nb][3] + biB[nb], 0.f);
        }
    }
    __syncthreads();

    // pooled: 4 py x 32 px x 16 co = 2048 outputs
#pragma unroll
    for (int pid = tid; pid < 2048; pid += 256) {
        int co = pid & 15;
        int px = (pid >> 4) & 31;
        int py = pid >> 9;
        int base = (2*py)*1024 + (2*px)*16 + co;
        float v = fmaxf(fmaxf(pool_s[base], pool_s[base+16]),
                        fmaxf(pool_s[base+1024], pool_s[base+1040]));
        int gpy = (oy0 >> 1) + py;
        int gpx = (ox0 >> 1) + px;
        if (gpy < HOUT/2 && gpx < WOUT/2) {
            float sc = bng[co] * rsqrtf(bnv[co] + BN_EPS);
            v = sc*(v - bnm[co]) + bnb[co];
            gout[((size_t)(b*CO + co)*(HOUT/2) + gpy)*(WOUT/2) + gpx] = v;
        }
    }
}

// ---------------- dense ----------------
__global__ void dense_k(const float* __restrict__ gm, const float* __restrict__ dw,
                        const float* __restrict__ db, float* __restrict__ h,
                        float* __restrict__ out_tail) {
    int b = threadIdx.x;
    if (b >= B) return;
    float s = db[0];
#pragma unroll
    for (int c = 0; c < 32; c++) s = fmaf(gm[b*32 + c], dw[c], s);
    h[b] = s;
    out_tail[b] = s;
}

// ---------------- geodesic reconstruction: 5 fused steps, 64x64 tile ----------------
#define RK 5
#define RT 64
#define RS (RT + 2*RK)
#define RCELL (RS*RS)
#define RNIT ((RCELL + 255)/256)
template<bool INIT>
__global__ __launch_bounds__(256)
void recon_k(const float* __restrict__ src, const float* __restrict__ mask,
             const float* __restrict__ h, float* __restrict__ dst) {
    __shared__ float sm[2][RCELL];
    int t = threadIdx.x;
    int ox = blockIdx.x*RT - RK;
    int oy = blockIdx.y*RT - RK;
    const size_t boff = (size_t)blockIdx.z*H0*W0;
    const float hv = INIT ? h[blockIdx.z] : 0.f;

    float mk[RNIT];
    bool  inter[RNIT];
#pragma unroll
    for (int k = 0; k < RNIT; k++) {
        int i = t + k*256;
        float sv = -CUDART_INF_F, mv = -CUDART_INF_F;
        bool it = false;
        if (i < RCELL) {
            int ly = i / RS, lx = i % RS;
            int gy = oy + ly, gx = ox + lx;
            if (gy >= 0 && gy < H0 && gx >= 0 && gx < W0) {
                mv = mask[boff + gy*W0 + gx];
                sv = INIT ? (mv - hv) : src[boff + gy*W0 + gx];
            }
            sm[0][i] = sv;
            it = (ly > 0 && ly < RS-1 && lx > 0 && lx < RS-1);
        }
        mk[k] = mv;
        inter[k] = it;
    }
    __syncthreads();
    int cur = 0;
#pragma unroll
    for (int step = 0; step < RK; step++) {
#pragma unroll
        for (int k = 0; k < RNIT; k++) {
            int i = t + k*256;
            if (i < RCELL) {
                float v;
                if (inter[k]) {
                    const float* s0 = &sm[cur][i];
                    float a = fmaxf(fmaxf(s0[-RS-1], s0[-RS]), s0[-RS+1]);
                    float c = fmaxf(fmaxf(s0[-1],    s0[0]),   s0[1]);
                    float d = fmaxf(fmaxf(s0[RS-1],  s0[RS]),  s0[RS+1]);
                    v = fminf(fmaxf(fmaxf(a, c), d), mk[k]);
                } else {
                    v = sm[cur][i];
                }
                sm[1-cur][i] = v;
            }
        }
        __syncthreads();
        cur ^= 1;
    }
    int tx = t & 63, tyq = t >> 6;
#pragma unroll
    for (int k = 0; k < 16; k++) {
        int r = tyq + 4*k;
        dst[boff + (size_t)(oy + RK + r)*W0 + (ox + RK + tx)] =
            sm[cur][(r + RK)*RS + (tx + RK)];
    }
}

// ---------------- launch ----------------
extern "C" void kernel_launch(void* const* d_in, const int* in_sizes, int n_in,
                              void* d_out, int out_size) {
    const float* x    = (const float*)d_in[0];
    const float* ko   = (const float*)d_in[1];
    const float* kc   = (const float*)d_in[2];
    const float* w1   = (const float*)d_in[3];
    const float* b1   = (const float*)d_in[4];
    const float* w2   = (const float*)d_in[5];
    const float* b2   = (const float*)d_in[6];
    const float* w3   = (const float*)d_in[7];
    const float* b3   = (const float*)d_in[8];
    const float* w4   = (const float*)d_in[9];
    const float* b4   = (const float*)d_in[10];
    const float* bn1g = (const float*)d_in[11];
    const float* bn1b = (const float*)d_in[12];
    const float* bn1m = (const float*)d_in[13];
    const float* bn1v = (const float*)d_in[14];
    const float* bn2g = (const float*)d_in[15];
    const float* bn2b = (const float*)d_in[16];
    const float* bn2m = (const float*)d_in[17];
    const float* bn2v = (const float*)d_in[18];
    const float* bn3g = (const float*)d_in[19];
    const float* bn3b = (const float*)d_in[20];
    const float* bn3m = (const float*)d_in[21];
    const float* bn3v = (const float*)d_in[22];
    const float* dw   = (const float*)d_in[23];
    const float* db   = (const float*)d_in[24];
    float* out = (float*)d_out;

    float *MA, *MB, *XC, *Y1, *Y2, *Y3, *GM, *HH;
    cudaGetSymbolAddress((void**)&MA, g_MA);
    cudaGetSymbolAddress((void**)&MB, g_MB);
    cudaGetSymbolAddress((void**)&XC, g_XC);
    cudaGetSymbolAddress((void**)&Y1, g_Y1);
    cudaGetSymbolAddress((void**)&Y2, g_Y2);
    cudaGetSymbolAddress((void**)&Y3, g_Y3);
    cudaGetSymbolAddress((void**)&GM, g_GM);
    cudaGetSymbolAddress((void**)&HH, g_H);

    cudaFuncSetAttribute(tconv_k<16,126,126,1>,
        cudaFuncAttributeMaxDynamicSharedMemorySize, TCONV_SHM);
    cudaFuncSetAttribute(tconv_k<32,124,124,2>,
        cudaFuncAttributeMaxDynamicSharedMemorySize, TCONV_SHM);

    // fused morphology -> XC
    morph4_k<<<dim3(4, 4, B), 256>>>(x, XC, ko, kc);

    // CNN
    conv1_k<<<dim3(254, B), 256>>>(XC, w1, b1, bn1g, bn1b, bn1m, bn1v, Y1);
    tconv2_k<<<dim3(4, 32, B), 256>>>(Y1, w2, b2, bn2g, bn2b, bn2m, bn2v, Y2);
    tconv_k<16, 126, 126, 1><<<dim3(2, 16, B), 256, TCONV_SHM>>>(
        Y2, w3, b3, bn3g, bn3b, bn3m, bn3v, Y3);
    cudaMemsetAsync(GM, 0, B*32*sizeof(float));
    tconv_k<32, 124, 124, 2><<<dim3(2, 16, B), 256, TCONV_SHM>>>(
        Y3, w4, b4, nullptr, nullptr, nullptr, nullptr, GM);
    dense_k<<<1, 32>>>(GM, dw, db, HH, out + (size_t)NPIX);

    // h-maxima: 50 steps = 10 launches of 5 fused steps (first fuses marker init)
    recon_k<true><<<dim3(4, 4, B), 256>>>(XC, XC, HH, MB);
    for (int l = 1; l < 10; l++) {
        float* srcp = (l & 1) ? MB : MA;
        float* dstp = (l == 9) ? out : ((l & 1) ? MA : MB);
        recon_k<false><<<dim3(4, 4, B), 256>>>(srcp, XC, nullptr, dstp);
    }
}

// round 8
// speedup vs baseline: 5.2746x; 1.0257x over previous
#include <cuda_runtime.h>
#include <math_constants.h>

#define B 32
#define H0 256
#define W0 256
#define NPIX (B*H0*W0)
#define BN_EPS 1e-3f

typedef unsigned long long u64t;

__device__ __forceinline__ u64t pk2(float a, float b) {
    u64t r; asm("mov.b64 %0,{%1,%2};" : "=l"(r) : "f"(a), "f"(b)); return r;
}
__device__ __forceinline__ void upk2(u64t v, float& a, float& b) {
    asm("mov.b64 {%0,%1},%2;" : "=f"(a), "=f"(b) : "l"(v));
}
__device__ __forceinline__ void fma2(u64t& d, u64t a, u64t b) {
    asm("fma.rn.f32x2 %0,%1,%2,%0;" : "+l"(d) : "l"(a), "l"(b));
}
__device__ __forceinline__ unsigned tf32r(float v) {
    unsigned r; asm("cvt.rna.tf32.f32 %0,%1;" : "=r"(r) : "f"(v)); return r;
}
#define MMA_TF32(d, a0,a1,a2,a3, b0,b1) \
    asm volatile("mma.sync.aligned.m16n8k8.row.col.f32.tf32.tf32.f32 " \
        "{%0,%1,%2,%3},{%4,%5,%6,%7},{%8,%9},{%0,%1,%2,%3};" \
        : "+f"((d)[0]),"+f"((d)[1]),"+f"((d)[2]),"+f"((d)[3]) \
        : "r"(a0),"r"(a1),"r"(a2),"r"(a3),"r"(b0),"r"(b1))

// ---------------- scratch ----------------
__device__ float g_MA[NPIX];
__device__ float g_MB[NPIX];
__device__ float g_XC[NPIX];
__device__ float g_Y1[(size_t)B*8*254*254];
__device__ float g_Y2[(size_t)B*16*126*126];
__device__ float g_Y3[(size_t)B*32*124*124];
__device__ float g_GM[B*32];
__device__ float g_H[B];

// ---------------- fused 4-pass morphology: E(ko),D(ko),D(kc),E(kc), halo 4 ----------------
#define MT 64
#define MHL 4
#define MS (MT + 2*MHL)
#define MCELL (MS*MS)
#define MNIT ((MCELL + 255)/256)
__global__ __launch_bounds__(256)
void morph4_k(const float* __restrict__ x, float* __restrict__ xc,
              const float* __restrict__ ko, const float* __restrict__ kc) {
    __shared__ float sm[2][MCELL];
    __shared__ float sk[18];
    int t = threadIdx.x;
    if (t < 18) sk[t] = (t < 9) ? ko[t] : kc[t - 9];
    int ox = blockIdx.x*MT - MHL;
    int oy = blockIdx.y*MT - MHL;
    const size_t boff = (size_t)blockIdx.z*H0*W0;

    bool inb[MNIT], inter[MNIT];
#pragma unroll
    for (int k = 0; k < MNIT; k++) {
        int i = t + k*256;
        bool ib = false, it = false;
        if (i < MCELL) {
            int ly = i / MS, lx = i % MS;
            int gy = oy + ly, gx = ox + lx;
            ib = (gy >= 0 && gy < H0 && gx >= 0 && gx < W0);
            sm[0][i] = ib ? x[boff + gy*W0 + gx] : CUDART_INF_F;
            it = (ly > 0 && ly < MS-1 && lx > 0 && lx < MS-1);
        }
        inb[k] = ib; inter[k] = it;
    }
    __syncthreads();
    int cur = 0;
#pragma unroll
    for (int op = 0; op < 4; op++) {
        const bool ero = (op == 0 || op == 3);
        const int koff = (op < 2) ? 0 : 9;
        const float nextpad = (op >= 2) ? CUDART_INF_F : -CUDART_INF_F;
#pragma unroll
        for (int k = 0; k < MNIT; k++) {
            int i = t + k*256;
            if (i < MCELL) {
                float v;
                if (!inb[k]) {
                    v = nextpad;
                } else if (inter[k]) {
                    const float* s0 = &sm[cur][i];
                    if (ero) {
                        float m = s0[-MS-1] - sk[koff + 8];
                        m = fminf(m, s0[-MS  ] - sk[koff + 7]);
                        m = fminf(m, s0[-MS+1] - sk[koff + 6]);
                        m = fminf(m, s0[-1]    - sk[koff + 5]);
                        m = fminf(m, s0[0]     - sk[koff + 4]);
                        m = fminf(m, s0[1]     - sk[koff + 3]);
                        m = fminf(m, s0[MS-1]  - sk[koff + 2]);
                        m = fminf(m, s0[MS  ]  - sk[koff + 1]);
                        m = fminf(m, s0[MS+1]  - sk[koff + 0]);
                        v = m;
                    } else {
                        float m = s0[-MS-1] + sk[koff + 0];
                        m = fmaxf(m, s0[-MS  ] + sk[koff + 1]);
                        m = fmaxf(m, s0[-MS+1] + sk[koff + 2]);
                        m = fmaxf(m, s0[-1]    + sk[koff + 3]);
                        m = fmaxf(m, s0[0]     + sk[koff + 4]);
                        m = fmaxf(m, s0[1]     + sk[koff + 5]);
                        m = fmaxf(m, s0[MS-1]  + sk[koff + 6]);
                        m = fmaxf(m, s0[MS  ]  + sk[koff + 7]);
                        m = fmaxf(m, s0[MS+1]  + sk[koff + 8]);
                        v = m;
                    }
                } else {
                    v = sm[cur][i];
                }
                sm[1-cur][i] = v;
            }
        }
        __syncthreads();
        cur ^= 1;
    }
    int tx = t & 63, tyq = t >> 6;
#pragma unroll
    for (int k = 0; k < 16; k++) {
        int r = tyq + 4*k;
        xc[boff + (size_t)(oy + MHL + r)*W0 + (ox + MHL + tx)] =
            sm[cur][(r + MHL)*MS + (tx + MHL)];
    }
}

// ---------------- conv1 (1->8) + relu + bn1 ----------------
__global__ void conv1_k(const float* __restrict__ xc, const float* __restrict__ w,
                        const float* __restrict__ bias,
                        const float* __restrict__ gg, const float* __restrict__ bb,
                        const float* __restrict__ mm, const float* __restrict__ vv,
                        float* __restrict__ out) {
    __shared__ float ws[72];
    int t = threadIdx.x;
    if (t < 72) ws[t] = w[t];
    __syncthreads();
    int y = blockIdx.x, b = blockIdx.y;
    int x = t;
    if (x >= 254) return;
    const float* base = xc + ((size_t)b*H0 + y)*W0 + x;
    u64t acc[4];
#pragma unroll
    for (int p = 0; p < 4; p++) acc[p] = pk2(bias[2*p], bias[2*p+1]);
#pragma unroll
    for (int tap = 0; tap < 9; tap++) {
        float v = base[(tap/3)*W0 + (tap%3)];
        u64t pv = pk2(v, v);
        const u64t* wq = (const u64t*)(ws + tap*8);
#pragma unroll
        for (int p = 0; p < 4; p++) fma2(acc[p], pv, wq[p]);
    }
#pragma unroll
    for (int p = 0; p < 4; p++) {
        float a0, a1; upk2(acc[p], a0, a1);
        int k0 = 2*p, k1 = 2*p+1;
        float s0 = gg[k0] * rsqrtf(vv[k0] + BN_EPS);
        float s1 = gg[k1] * rsqrtf(vv[k1] + BN_EPS);
        out[((size_t)(b*8 + k0)*254 + y)*254 + x] = s0*(fmaxf(a0,0.f) - mm[k0]) + bb[k0];
        out[((size_t)(b*8 + k1)*254 + y)*254 + x] = s1*(fmaxf(a1,0.f) - mm[k1]) + bb[k1];
    }
}

// ================= tensor tf32 convs =================
// lane mapping: kq = lane&3 (k-quad row), nr = lane>>2 (n/m group)
// Packed B layout: per (tap,cib), lane's 8 words contiguous: [nb0k0,nb0k1,nb1k0,nb1k1,nb2k0,...]

// ---------------- conv3/conv4: TW=32, CO=32, static smem ----------------
// MODE 1: store bn(relu(conv+b))   MODE 2: global atomic max of relu(conv+b)
template<int CI, int HIN, int WIN, int MODE>
__global__ __launch_bounds__(256)
void tconv_k(const float* __restrict__ gin, const float* __restrict__ gw,
             const float* __restrict__ gb,
             const float* __restrict__ bng, const float* __restrict__ bnb,
             const float* __restrict__ bnm, const float* __restrict__ bnv,
             float* __restrict__ gout) {
    constexpr int CO = 32;
    constexpr int HOUT = HIN - 2, WOUT = WIN - 2;
    constexpr int CC  = 16;
    constexpr int NCH = CI / CC;
    constexpr int STR = 36, PLANE = 360;

    __shared__ __align__(16) unsigned in_s[CC*PLANE];   // 5760
    __shared__ __align__(16) unsigned wp_s[9*2*32*8];   // 4608
    __shared__ float smax[CO];

    int tid = threadIdx.x;
    int warp = tid >> 5, lane = tid & 31;
    int kq = lane & 3, nr = lane >> 2;
    int ox0 = blockIdx.x * 32, oy0 = blockIdx.y * 8;
    int b = blockIdx.z;

    if (MODE == 2 && tid < CO) smax[tid] = 0.f;

    float acc[2][4][4];
#pragma unroll
    for (int j = 0; j < 2; j++)
#pragma unroll
        for (int nb = 0; nb < 4; nb++)
#pragma unroll
            for (int q = 0; q < 4; q++) acc[j][nb][q] = 0.f;

    for (int cc = 0; cc < NCH; cc++) {
        __syncthreads();
        // input tile: CC x 10 x 34, tf32
        for (int idx = tid; idx < CC*340; idx += 256) {
            int ci = idx / 340, rem = idx % 340;
            int yy = rem / 34, xx = rem % 34;
            int gy = oy0 + yy, gx = ox0 + xx;
            float v = 0.f;
            if (gy < HIN && gx < WIN)
                v = gin[((size_t)(b*CI + cc*CC + ci)*HIN + gy)*WIN + gx];
            in_s[ci*PLANE + yy*STR + xx] = tf32r(v);
        }
        // packed weights: dst idx -> (tap,cib,lane(kq,nr),nb,kh)
        for (int idx = tid; idx < 9*2*32*8; idx += 256) {
            int val = idx & 7;
            int knb = val >> 1, kkh = val & 1;
            int ln  = (idx >> 3) & 31;
            int lkq = ln & 3, lnr = ln >> 2;
            int ct  = idx >> 8;
            int cib = ct & 1, tap = ct >> 1;
            int ci = cib*8 + lkq + 4*kkh;
            int co = knb*8 + lnr;
            wp_s[idx] = tf32r(gw[tap*(CI*CO) + (cc*CC + ci)*CO + co]);
        }
        __syncthreads();
#pragma unroll
        for (int tap = 0; tap < 9; tap++) {
            const int dy = tap/3, dx = tap%3;
#pragma unroll
            for (int cib = 0; cib < 2; cib++) {
                const uint4* wq = (const uint4*)(wp_s + ((tap*2 + cib)*32 + lane)*8);
                uint4 b01 = wq[0];
                uint4 b23 = wq[1];
                const unsigned* ia = in_s + (cib*8 + kq)*PLANE + (warp+dy)*STR + dx + nr;
#pragma unroll
                for (int j = 0; j < 2; j++) {
                    unsigned a0 = ia[j*16];
                    unsigned a1 = ia[j*16 + 8];
                    unsigned a2 = ia[j*16 + 4*PLANE];
                    unsigned a3 = ia[j*16 + 4*PLANE + 8];
                    MMA_TF32(acc[j][0], a0, a1, a2, a3, b01.x, b01.y);
                    MMA_TF32(acc[j][1], a0, a1, a2, a3, b01.z, b01.w);
                    MMA_TF32(acc[j][2], a0, a1, a2, a3, b23.x, b23.y);
                    MMA_TF32(acc[j][3], a0, a1, a2, a3, b23.z, b23.w);
                }
            }
        }
    }

    // epilogue: thread holds (y=oy0+warp; x = ox0+16j+nr (+8); co = nb*8+2kq (+1))
    int y = oy0 + warp;
    float biA[4], biB[4];
#pragma unroll
    for (int nb = 0; nb < 4; nb++) {
        biA[nb] = gb[nb*8 + 2*kq];
        biB[nb] = gb[nb*8 + 2*kq + 1];
    }

    if (MODE == 2) {
        float lm[4][2];
#pragma unroll
        for (int nb = 0; nb < 4; nb++) { lm[nb][0] = 0.f; lm[nb][1] = 0.f; }
        if (y < HOUT) {
#pragma unroll
            for (int j = 0; j < 2; j++) {
                int xA = ox0 + j*16 + nr;
                int xB = xA + 8;
#pragma unroll
                for (int nb = 0; nb < 4; nb++) {
                    if (xA < WOUT) {
                        lm[nb][0] = fmaxf(lm[nb][0], acc[j][nb][0] + biA[nb]);
                        lm[nb][1] = fmaxf(lm[nb][1], acc[j][nb][1] + biB[nb]);
                    }
                    if (xB < WOUT) {
                        lm[nb][0] = fmaxf(lm[nb][0], acc[j][nb][2] + biA[nb]);
                        lm[nb][1] = fmaxf(lm[nb][1], acc[j][nb][3] + biB[nb]);
                    }
                }
            }
        }
#pragma unroll
        for (int nb = 0; nb < 4; nb++) {
            atomicMax((int*)&smax[nb*8 + 2*kq],     __float_as_int(fmaxf(lm[nb][0], 0.f)));
            atomicMax((int*)&smax[nb*8 + 2*kq + 1], __float_as_int(fmaxf(lm[nb][1], 0.f)));
        }
        __syncthreads();
        if (tid < CO)
            atomicMax((int*)&gout[b*CO + tid], __float_as_int(smax[tid]));
    } else {
        if (y < HOUT) {
#pragma unroll
            for (int nb = 0; nb < 4; nb++) {
                int coA = nb*8 + 2*kq, coB = coA + 1;
                float scA = bng[coA] * rsqrtf(bnv[coA] + BN_EPS);
                float scB = bng[coB] * rsqrtf(bnv[coB] + BN_EPS);
                float sbA = bnb[coA], sbB = bnb[coB];
                float smA = bnm[coA], smB = bnm[coB];
                float* pA = gout + ((size_t)(b*CO + coA)*HOUT + y)*WOUT;
                float* pB = gout + ((size_t)(b*CO + coB)*HOUT + y)*WOUT;
#pragma unroll
                for (int j = 0; j < 2; j++) {
                    int xA = ox0 + j*16 + nr;
                    int xB = xA + 8;
                    if (xA < WOUT) {
                        pA[xA] = scA*(fmaxf(acc[j][nb][0] + biA[nb], 0.f) - smA) + sbA;
                        pB[xA] = scB*(fmaxf(acc[j][nb][1] + biB[nb], 0.f) - smB) + sbB;
                    }
                    if (xB < WOUT) {
                        pA[xB] = scA*(fmaxf(acc[j][nb][2] + biA[nb], 0.f) - smA) + sbA;
                        pB[xB] = scB*(fmaxf(acc[j][nb][3] + biB[nb], 0.f) - smB) + sbB;
                    }
                }
            }
        }
    }
}

// ---------------- conv2 tensor: CI=8, CO=16, TW=64, fused maxpool2+bn ----------------
#define T2STR   68
#define T2PLANE 680
__global__ __launch_bounds__(256)
void tconv2_k(const float* __restrict__ gin, const float* __restrict__ gw,
              const float* __restrict__ gb,
              const float* __restrict__ bng, const float* __restrict__ bnb,
              const float* __restrict__ bnm, const float* __restrict__ bnv,
              float* __restrict__ gout) {
    constexpr int CI = 8, CO = 16;
    constexpr int HIN = 254, WIN = 254;
    constexpr int HOUT = 252, WOUT = 252;
    constexpr int LW = 66;

    __shared__ __align__(16) unsigned shm2[8192];  // in_s(5440)+wp(1152) | pool(8192)
    unsigned* in_s = shm2;
    unsigned* wp_s = shm2 + CI*T2PLANE;
    float* pool_s  = (float*)shm2;

    int tid = threadIdx.x;
    int warp = tid >> 5, lane = tid & 31;
    int kq = lane & 3, nr = lane >> 2;
    int ox0 = blockIdx.x * 64, oy0 = blockIdx.y * 8;
    int b = blockIdx.z;

    float acc[4][2][4];
#pragma unroll
    for (int j = 0; j < 4; j++)
#pragma unroll
        for (int nb = 0; nb < 2; nb++)
#pragma unroll
            for (int q = 0; q < 4; q++) acc[j][nb][q] = 0.f;

    for (int idx = tid; idx < CI*10*LW; idx += 256) {
        int ci = idx / (10*LW), rem = idx % (10*LW);
        int yy = rem / LW, xx = rem % LW;
        int gy = oy0 + yy, gx = ox0 + xx;
        float v = 0.f;
        if (gy < HIN && gx < WIN)
            v = gin[((size_t)(b*CI + ci)*HIN + gy)*WIN + gx];
        in_s[ci*T2PLANE + yy*T2STR + xx] = tf32r(v);
    }
    // packed weights: idx -> (tap, lane(kq,nr), nb, kh)
    for (int idx = tid; idx < 9*32*4; idx += 256) {
        int val = idx & 3;
        int knb = val >> 1, kkh = val & 1;
        int ln  = (idx >> 2) & 31;
        int lkq = ln & 3, lnr = ln >> 2;
        int tap = idx >> 7;
        int ci = lkq + 4*kkh;
        int co = knb*8 + lnr;
        wp_s[idx] = tf32r(gw[tap*(CI*CO) + ci*CO + co]);
    }
    __syncthreads();
#pragma unroll
    for (int tap = 0; tap < 9; tap++) {
        const int dy = tap/3, dx = tap%3;
        uint4 bq = *(const uint4*)(wp_s + (tap*32 + lane)*4);
        const unsigned* ia = in_s + kq*T2PLANE + (warp+dy)*T2STR + dx + nr;
#pragma unroll
        for (int j = 0; j < 4; j++) {
            unsigned a0 = ia[j*16];
            unsigned a1 = ia[j*16 + 8];
            unsigned a2 = ia[j*16 + 4*T2PLANE];
            unsigned a3 = ia[j*16 + 4*T2PLANE + 8];
            MMA_TF32(acc[j][0], a0, a1, a2, a3, bq.x, bq.y);
            MMA_TF32(acc[j][1], a0, a1, a2, a3, bq.z, bq.w);
        }
    }

    // relu(conv+b) -> pool_s[y(8)][x(64)][co(16)]
    float biA[2], biB[2];
#pragma unroll
    for (int nb = 0; nb < 2; nb++) {
        biA[nb] = gb[nb*8 + 2*kq];
        biB[nb] = gb[nb*8 + 2*kq + 1];
    }
    __syncthreads();
#pragma unroll
    for (int j = 0; j < 4; j++) {
        int xA = j*16 + nr, xB = xA + 8;
#pragma unroll
        for (int nb = 0; nb < 2; nb++) {
            int coA = nb*8 + 2*kq, coB = coA + 1;
            pool_s[warp*1024 + xA*16 + coA] = fmaxf(acc[j][nb][0] + biA[nb], 0.f);
            pool_s[warp*1024 + xA*16 + coB] = fmaxf(acc[j][nb][1] + biB[nb], 0.f);
            pool_s[warp*1024 + xB*16 + coA] = fmaxf(acc[j][nb][2] + biA[nb], 0.f);
            pool_s[warp*1024 + xB*16 + coB] = fmaxf(acc[j][nb][3] + biB[nb], 0.f);
        }
    }
    __syncthreads();

#pragma unroll
    for (int pid = tid; pid < 2048; pid += 256) {
        int co = pid & 15;
        int px = (pid >> 4) & 31;
        int py = pid >> 9;
        int base = (2*py)*1024 + (2*px)*16 + co;
        float v = fmaxf(fmaxf(pool_s[base], pool_s[base+16]),
                        fmaxf(pool_s[base+1024], pool_s[base+1040]));
        int gpy = (oy0 >> 1) + py;
        int gpx = (ox0 >> 1) + px;
        if (gpy < HOUT/2 && gpx < WOUT/2) {
            float sc = bng[co] * rsqrtf(bnv[co] + BN_EPS);
            v = sc*(v - bnm[co]) + bnb[co];
            gout[((size_t)(b*CO + co)*(HOUT/2) + gpy)*(WOUT/2) + gpx] = v;
        }
    }
}

// ---------------- dense ----------------
__global__ void dense_k(const float* __restrict__ gm, const float* __restrict__ dw,
                        const float* __restrict__ db, float* __restrict__ h,
                        float* __restrict__ out_tail) {
    int b = threadIdx.x;
    if (b >= B) return;
    float s = db[0];
#pragma unroll
    for (int c = 0; c < 32; c++) s = fmaf(gm[b*32 + c], dw[c], s);
    h[b] = s;
    out_tail[b] = s;
}

// ---------------- geodesic reconstruction: 5 fused steps, 64x64 tile ----------------
#define RK 5
#define RT 64
#define RS (RT + 2*RK)
#define RCELL (RS*RS)
#define RNIT ((RCELL + 255)/256)
template<bool INIT>
__global__ __launch_bounds__(256)
void recon_k(const float* __restrict__ src, const float* __restrict__ mask,
             const float* __restrict__ h, float* __restrict__ dst) {
    __shared__ float sm[2][RCELL];
    int t = threadIdx.x;
    int ox = blockIdx.x*RT - RK;
    int oy = blockIdx.y*RT - RK;
    const size_t boff = (size_t)blockIdx.z*H0*W0;
    const float hv = INIT ? h[blockIdx.z] : 0.f;

    float mk[RNIT];
    bool  inter[RNIT];
#pragma unroll
    for (int k = 0; k < RNIT; k++) {
        int i = t + k*256;
        float sv = -CUDART_INF_F, mv = -CUDART_INF_F;
        bool it = false;
        if (i < RCELL) {
            int ly = i / RS, lx = i % RS;
            int gy = oy + ly, gx = ox + lx;
            if (gy >= 0 && gy < H0 && gx >= 0 && gx < W0) {
                mv = mask[boff + gy*W0 + gx];
                sv = INIT ? (mv - hv) : src[boff + gy*W0 + gx];
            }
            sm[0][i] = sv;
            it = (ly > 0 && ly < RS-1 && lx > 0 && lx < RS-1);
        }
        mk[k] = mv;
        inter[k] = it;
    }
    __syncthreads();
    int cur = 0;
#pragma unroll
    for (int step = 0; step < RK; step++) {
#pragma unroll
        for (int k = 0; k < RNIT; k++) {
            int i = t + k*256;
            if (i < RCELL) {
                float v;
                if (inter[k]) {
                    const float* s0 = &sm[cur][i];
                    float a = fmaxf(fmaxf(s0[-RS-1], s0[-RS]), s0[-RS+1]);
                    float c = fmaxf(fmaxf(s0[-1],    s0[0]),   s0[1]);
                    float d = fmaxf(fmaxf(s0[RS-1],  s0[RS]),  s0[RS+1]);
                    v = fminf(fmaxf(fmaxf(a, c), d), mk[k]);
                } else {
                    v = sm[cur][i];
                }
                sm[1-cur][i] = v;
            }
        }
        __syncthreads();
        cur ^= 1;
    }
    int tx = t & 63, tyq = t >> 6;
#pragma unroll
    for (int k = 0; k < 16; k++) {
        int r = tyq + 4*k;
        dst[boff + (size_t)(oy + RK + r)*W0 + (ox + RK + tx)] =
            sm[cur][(r + RK)*RS + (tx + RK)];
    }
}

// ---------------- launch ----------------
extern "C" void kernel_launch(void* const* d_in, const int* in_sizes, int n_in,
                              void* d_out, int out_size) {
    const float* x    = (const float*)d_in[0];
    const float* ko   = (const float*)d_in[1];
    const float* kc   = (const float*)d_in[2];
    const float* w1   = (const float*)d_in[3];
    const float* b1   = (const float*)d_in[4];
    const float* w2   = (const float*)d_in[5];
    const float* b2   = (const float*)d_in[6];
    const float* w3   = (const float*)d_in[7];
    const float* b3   = (const float*)d_in[8];
    const float* w4   = (const float*)d_in[9];
    const float* b4   = (const float*)d_in[10];
    const float* bn1g = (const float*)d_in[11];
    const float* bn1b = (const float*)d_in[12];
    const float* bn1m = (const float*)d_in[13];
    const float* bn1v = (const float*)d_in[14];
    const float* bn2g = (const float*)d_in[15];
    const float* bn2b = (const float*)d_in[16];
    const float* bn2m = (const float*)d_in[17];
    const float* bn2v = (const float*)d_in[18];
    const float* bn3g = (const float*)d_in[19];
    const float* bn3b = (const float*)d_in[20];
    const float* bn3m = (const float*)d_in[21];
    const float* bn3v = (const float*)d_in[22];
    const float* dw   = (const float*)d_in[23];
    const float* db   = (const float*)d_in[24];
    float* out = (float*)d_out;

    float *MA, *MB, *XC, *Y1, *Y2, *Y3, *GM, *HH;
    cudaGetSymbolAddress((void**)&MA, g_MA);
    cudaGetSymbolAddress((void**)&MB, g_MB);
    cudaGetSymbolAddress((void**)&XC, g_XC);
    cudaGetSymbolAddress((void**)&Y1, g_Y1);
    cudaGetSymbolAddress((void**)&Y2, g_Y2);
    cudaGetSymbolAddress((void**)&Y3, g_Y3);
    cudaGetSymbolAddress((void**)&GM, g_GM);
    cudaGetSymbolAddress((void**)&HH, g_H);

    // fused morphology -> XC
    morph4_k<<<dim3(4, 4, B), 256>>>(x, XC, ko, kc);

    // CNN
    conv1_k<<<dim3(254, B), 256>>>(XC, w1, b1, bn1g, bn1b, bn1m, bn1v, Y1);
    tconv2_k<<<dim3(4, 32, B), 256>>>(Y1, w2, b2, bn2g, bn2b, bn2m, bn2v, Y2);
    tconv_k<16, 126, 126, 1><<<dim3(4, 16, B), 256>>>(
        Y2, w3, b3, bn3g, bn3b, bn3m, bn3v, Y3);
    cudaMemsetAsync(GM, 0, B*32*sizeof(float));
    tconv_k<32, 124, 124, 2><<<dim3(4, 16, B), 256>>>(
        Y3, w4, b4, nullptr, nullptr, nullptr, nullptr, GM);
    dense_k<<<1, 32>>>(GM, dw, db, HH, out + (size_t)NPIX);

    // h-maxima: 50 steps = 10 launches of 5 fused steps (first fuses marker init)
    recon_k<true><<<dim3(4, 4, B), 256>>>(XC, XC, HH, MB);
    for (int l = 1; l < 10; l++) {
        float* srcp = (l & 1) ? MB : MA;
        float* dstp = (l == 9) ? out : ((l & 1) ? MA : MB);
        recon_k<false><<<dim3(4, 4, B), 256>>>(srcp, XC, nullptr, dstp);
    }
}